// round 7
// baseline (speedup 1.0000x reference)
#include <cuda_runtime.h>
#include <cuda_bf16.h>
#include <cuda_fp16.h>
#include <math.h>
#include <stdint.h>

// Problem constants
#define CB   4
#define CS   1024
#define CDM  1024
#define CH   16
#define CDK  64
#define CBH  (CB*CH)

// ---------------- scratch (device globals: allocation-free) ----------------
__device__ float g_scores[(size_t)CBH*CS*CS];            // 256 MB fp32
__device__ __half g_ps [(size_t)CBH*CS*CS];              // 128 MB fp16 (P)
__device__ __half g_vts[2*(size_t)CBH*CDK*CS];           // V^T fp16 hi/lo
__device__ __half g_qhs[(size_t)CBH*CS*CDK];             // Q fp16 (hi only)
__device__ __half g_khs[2*(size_t)CBH*CS*CDK];           // K fp16 hi/lo
__device__ __nv_bfloat16 g_qs [2*(size_t)CB*CS*CDM];
__device__ __nv_bfloat16 g_ks [2*(size_t)CB*CS*CDM];
__device__ __nv_bfloat16 g_vs [2*(size_t)CB*CS*CDM];
__device__ __nv_bfloat16 g_ccs[2*(size_t)CB*CS*CDM];
__device__ __nv_bfloat16 g_wqs[2*(size_t)CDM*CDM];
__device__ __nv_bfloat16 g_wks[2*(size_t)CDM*CDM];
__device__ __nv_bfloat16 g_wvs[2*(size_t)CDM*CDM];
__device__ __nv_bfloat16 g_wos[2*(size_t)CDM*CDM];

// ============================================================================
// helpers
// ============================================================================
__device__ __forceinline__ uint32_t smem_u32(const void* p) {
    uint32_t a;
    asm("{ .reg .u64 t; cvta.to.shared.u64 t, %1; cvt.u32.u64 %0, t; }"
        : "=r"(a) : "l"(p));
    return a;
}
__device__ __forceinline__ void cp_async16(uint32_t dst, const void* src) {
    asm volatile("cp.async.cg.shared.global [%0], [%1], 16;"
                 :: "r"(dst), "l"(src) : "memory");
}
__device__ __forceinline__ void cp_commit() {
    asm volatile("cp.async.commit_group;" ::: "memory");
}
template<int N>
__device__ __forceinline__ void cp_wait() {
    asm volatile("cp.async.wait_group %0;" :: "n"(N) : "memory");
}
__device__ __forceinline__ void ldm4(uint32_t* r, uint32_t addr) {
    asm volatile("ldmatrix.sync.aligned.m8n8.x4.shared.b16 {%0,%1,%2,%3}, [%4];"
                 : "=r"(r[0]), "=r"(r[1]), "=r"(r[2]), "=r"(r[3]) : "r"(addr));
}
__device__ __forceinline__ void mma_bf16(float* c, const uint32_t* a, const uint32_t* b) {
    asm volatile(
        "mma.sync.aligned.m16n8k16.row.col.f32.bf16.bf16.f32 "
        "{%0,%1,%2,%3}, {%4,%5,%6,%7}, {%8,%9}, {%0,%1,%2,%3};"
        : "+f"(c[0]), "+f"(c[1]), "+f"(c[2]), "+f"(c[3])
        : "r"(a[0]), "r"(a[1]), "r"(a[2]), "r"(a[3]), "r"(b[0]), "r"(b[1]));
}
__device__ __forceinline__ void mma_f16(float* c, const uint32_t* a, const uint32_t* b) {
    asm volatile(
        "mma.sync.aligned.m16n8k16.row.col.f32.f16.f16.f32 "
        "{%0,%1,%2,%3}, {%4,%5,%6,%7}, {%8,%9}, {%0,%1,%2,%3};"
        : "+f"(c[0]), "+f"(c[1]), "+f"(c[2]), "+f"(c[3])
        : "r"(a[0]), "r"(a[1]), "r"(a[2]), "r"(a[3]), "r"(b[0]), "r"(b[1]));
}

// ============================================================================
// Combined split: all 7 tensors (q,k,v: 4M elems; Wq,Wk,Wv,Wo: 1M elems)
// in one launch. i4 indexes float4 groups, 4M groups total.
// ============================================================================
struct SplitPack {
    const float*   src[7];
    __nv_bfloat16* dst[7];
};

__global__ void __launch_bounds__(256) split_all_kernel(SplitPack p)
{
    const long i4 = (long)blockIdx.x * 256 + threadIdx.x;   // 0 .. 2^22-1
    int t; long off4;
    if (i4 < 3145728L) {                    // q,k,v : 2^20 groups each
        t = (int)(i4 >> 20);
        off4 = i4 - ((long)t << 20);
    } else {                                // weights : 2^18 groups each
        int u = (int)((i4 - 3145728L) >> 18);
        t = 3 + u;
        off4 = (i4 - 3145728L) - ((long)u << 18);
    }
    const long n = (t < 3) ? 4194304L : 1048576L;
    const long i = off4 * 4;
    float4 v = *(const float4*)(p.src[t] + i);
    float f[4] = {v.x, v.y, v.z, v.w};
    __nv_bfloat16 h[4], l[4];
    #pragma unroll
    for (int j = 0; j < 4; j++) {
        h[j] = __float2bfloat16(f[j]);
        l[j] = __float2bfloat16(f[j] - __bfloat162float(h[j]));
    }
    *(uint2*)(p.dst[t] + i)     = *(uint2*)h;
    *(uint2*)(p.dst[t] + n + i) = *(uint2*)l;
}

// ============================================================================
// HMMA GEMM core (bf16-split x3 combos). Shared by the fused QKV projection
// kernel (runtime out-mode per blockIdx.z) and the output projection.
// out modes: 0 fp32 row-major; 3 fp16 hi/lo transposed head-scatter;
//            4 fp16 single plane head-scatter; 5 fp16 hi/lo head-scatter.
// ============================================================================
#define ROWB 80
#define PLANE 10240
#define BUF   (4*PLANE)
#define MM_SMEM (2*BUF)

struct ProjPack {
    const __nv_bfloat16* A[3];
    const __nv_bfloat16* B[3];
    const float*         bias[3];
    void*                out[3];
    long                 PL[3];
    int                  mode[3];
};

__device__ __forceinline__ void gemm_core_128x128(
    const __nv_bfloat16* A, long loA,
    const __nv_bfloat16* B, long loB,
    int K, uint32_t sbase, int tid, float acc[2][8][4])
{
    const int warp = tid >> 5;
    const int lane = tid & 31;
    const int wm   = warp & 3;
    const int wn   = warp >> 2;
    const int lane8 = lane & 7;
    const int lg    = lane >> 3;

    const __nv_bfloat16* bases[4];
    bases[0] = A;
    bases[1] = A + loA;
    bases[2] = B;
    bases[3] = B + loB;

    const int nch = K >> 5;

    auto load_chunk = [&](int ic, int b) {
        const int k0 = ic * 32;
        #pragma unroll
        for (int i = 0; i < 8; i++) {
            int seg = i * 256 + tid;
            int p   = seg >> 9;
            int r   = (seg >> 2) & 127;
            int c   = seg & 3;
            const __nv_bfloat16* src = bases[p] + (size_t)r * K + k0 + c * 8;
            uint32_t dst = sbase + b * BUF + p * PLANE + r * ROWB + c * 16;
            cp_async16(dst, src);
        }
        cp_commit();
    };

    load_chunk(0, 0);
    if (nch > 1) load_chunk(1, 1);

    for (int ic = 0; ic < nch; ic++) {
        const int b = ic & 1;
        if (ic == nch - 1) cp_wait<0>(); else cp_wait<1>();
        __syncthreads();

        const uint32_t bb = sbase + b * BUF;
        #pragma unroll
        for (int kk = 0; kk < 2; kk++) {
            uint32_t ah[2][4], al[2][4];
            #pragma unroll
            for (int tm = 0; tm < 2; tm++) {
                int row = wm * 32 + tm * 16 + lane8 + (lg & 1) * 8;
                int col = kk * 32 + (lg >> 1) * 16;
                uint32_t addr = bb + row * ROWB + col;
                ldm4(ah[tm], addr);
                ldm4(al[tm], addr + PLANE);
            }
            #pragma unroll
            for (int tp = 0; tp < 4; tp++) {
                uint32_t bhf[4], blf[4];
                int row = wn * 64 + tp * 16 + lane8 + (lg >> 1) * 8;
                int col = kk * 32 + (lg & 1) * 16;
                uint32_t addr = bb + 2 * PLANE + row * ROWB + col;
                ldm4(bhf, addr);
                ldm4(blf, addr + PLANE);
                #pragma unroll
                for (int tm = 0; tm < 2; tm++) {
                    #pragma unroll
                    for (int h2 = 0; h2 < 2; h2++) {
                        float* c = acc[tm][tp * 2 + h2];
                        mma_bf16(c, ah[tm], bhf + h2 * 2);
                        mma_bf16(c, ah[tm], blf + h2 * 2);
                        mma_bf16(c, al[tm], bhf + h2 * 2);
                    }
                }
            }
        }
        __syncthreads();
        if (ic + 2 < nch) load_chunk(ic + 2, b);
    }
}

// Fused QKV projections: blockIdx.z in {0,1,2} -> (Q,K,V)
__global__ void __launch_bounds__(256, 1) proj_gemm_kernel(
    ProjPack p, long loA, long loB)
{
    extern __shared__ char smem[];
    const uint32_t sbase = smem_u32(smem);

    const int z  = blockIdx.z;
    const int m0 = blockIdx.y * 128;
    const int n0 = blockIdx.x * 128;
    const int tid = threadIdx.x;

    float acc[2][8][4];
    #pragma unroll
    for (int i = 0; i < 2; i++)
        #pragma unroll
        for (int j = 0; j < 8; j++)
            #pragma unroll
            for (int c = 0; c < 4; c++) acc[i][j][c] = 0.f;

    gemm_core_128x128(p.A[z] + (size_t)m0 * CDM, loA,
                      p.B[z] + (size_t)n0 * CDM, loB,
                      CDM, sbase, tid, acc);

    const int warp = tid >> 5;
    const int lane = tid & 31;
    const int wm   = warp & 3;
    const int wn   = warp >> 2;
    const int gid  = lane >> 2;
    const int tig  = lane & 3;
    const float* bias = p.bias[z];
    const int mode = p.mode[z];
    const long PL  = p.PL[z];
    __half* P = (__half*)p.out[z];

    #pragma unroll
    for (int tm = 0; tm < 2; tm++) {
        #pragma unroll
        for (int tn = 0; tn < 8; tn++) {
            float* c = acc[tm][tn];
            const int m = m0 + wm * 32 + tm * 16 + gid;
            const int n = n0 + wn * 64 + tn * 8 + tig * 2;
            const float b0 = bias[n], b1 = bias[n + 1];
            float v00 = c[0] + b0, v01 = c[1] + b1;
            float v10 = c[2] + b0, v11 = c[3] + b1;
            const int h  = n >> 6;
            const int dk = n & 63;
            if (mode == 3) {            // V: fp16 hi/lo transposed
                #pragma unroll
                for (int rr = 0; rr < 2; rr++) {
                    const int mm = m + rr * 8;
                    const float va = rr ? v10 : v00, vb = rr ? v11 : v01;
                    const int b_ = mm >> 10, s = mm & 1023;
                    size_t base = (((size_t)(b_ * CH + h)) * CDK + dk) * CS + s;
                    __half ha = __float2half(va);
                    __half la = __float2half(va - __half2float(ha));
                    __half hb = __float2half(vb);
                    __half lb = __float2half(vb - __half2float(hb));
                    P[base]           = ha;
                    P[base + PL]      = la;
                    P[base + CS]      = hb;
                    P[base + CS + PL] = lb;
                }
            } else {                    // Q (4) / K (5): row-major head-scatter
                #pragma unroll
                for (int rr = 0; rr < 2; rr++) {
                    const int mm = m + rr * 8;
                    const float va = rr ? v10 : v00, vb = rr ? v11 : v01;
                    const int b_ = mm >> 10, s = mm & 1023;
                    size_t idx = (((size_t)(b_ * CH + h)) * CS + s) * CDK + dk;
                    __half ha = __float2half(va);
                    __half hb = __float2half(vb);
                    __half2 hp = __halves2half2(ha, hb);
                    *(uint32_t*)(P + idx) = *(uint32_t*)&hp;
                    if (mode == 5) {
                        __half la = __float2half(va - __half2float(ha));
                        __half lb = __float2half(vb - __half2float(hb));
                        __half2 lp = __halves2half2(la, lb);
                        *(uint32_t*)(P + PL + idx) = *(uint32_t*)&lp;
                    }
                }
            }
        }
    }
}

// Output projection: fp32 row-major out
__global__ void __launch_bounds__(256, 1) out_gemm_kernel(
    const __nv_bfloat16* __restrict__ A, long loA,
    const __nv_bfloat16* __restrict__ B, long loB,
    const float* __restrict__ bias, float* __restrict__ C)
{
    extern __shared__ char smem[];
    const uint32_t sbase = smem_u32(smem);

    const int m0 = blockIdx.y * 128;
    const int n0 = blockIdx.x * 128;
    const int tid = threadIdx.x;

    float acc[2][8][4];
    #pragma unroll
    for (int i = 0; i < 2; i++)
        #pragma unroll
        for (int j = 0; j < 8; j++)
            #pragma unroll
            for (int c = 0; c < 4; c++) acc[i][j][c] = 0.f;

    gemm_core_128x128(A + (size_t)m0 * CDM, loA,
                      B + (size_t)n0 * CDM, loB,
                      CDM, sbase, tid, acc);

    const int warp = tid >> 5;
    const int lane = tid & 31;
    const int wm   = warp & 3;
    const int wn   = warp >> 2;
    const int gid  = lane >> 2;
    const int tig  = lane & 3;
    #pragma unroll
    for (int tm = 0; tm < 2; tm++) {
        #pragma unroll
        for (int tn = 0; tn < 8; tn++) {
            float* c = acc[tm][tn];
            const int m = m0 + wm * 32 + tm * 16 + gid;
            const int n = n0 + wn * 64 + tn * 8 + tig * 2;
            const float b0 = bias[n], b1 = bias[n + 1];
            *(float2*)(C + (size_t)m * CDM + n)
                = make_float2(c[0] + b0, c[1] + b1);
            *(float2*)(C + (size_t)(m + 8) * CDM + n)
                = make_float2(c[2] + b0, c[3] + b1);
        }
    }
}

// ============================================================================
// QK^T scores kernel (fp16 Q hi x K hi/lo, 2 combos, K=64 single shot)
// ============================================================================
#define QKROWB 144
#define QKPLANE (128*QKROWB)
#define QK_SMEM (3*QKPLANE)

__global__ void __launch_bounds__(256, 1) qk_gemm_kernel(
    const __half* __restrict__ Qg,
    const __half* __restrict__ Kg, long PLK,
    float* __restrict__ S)
{
    extern __shared__ char smem[];
    const uint32_t sbase = smem_u32(smem);

    const int z  = blockIdx.z;
    const int m0 = blockIdx.y * 128;
    const int n0 = blockIdx.x * 128;
    const __half* Qz = Qg + ((size_t)z * CS + m0) * CDK;
    const __half* Kz = Kg + ((size_t)z * CS + n0) * CDK;
    float* Sz = S + (size_t)z * CS * CS;

    const int tid  = threadIdx.x;
    const int warp = tid >> 5;
    const int lane = tid & 31;
    const int wm   = warp & 3;
    const int wn   = warp >> 2;
    const int lane8 = lane & 7;
    const int lg    = lane >> 3;

    #pragma unroll
    for (int i = 0; i < 12; i++) {
        int seg = i * 256 + tid;
        int p   = seg >> 10;
        int r   = (seg >> 3) & 127;
        int c   = seg & 7;
        const __half* src;
        if (p == 0)      src = Qz + (size_t)r * CDK + c * 8;
        else if (p == 1) src = Kz + (size_t)r * CDK + c * 8;
        else             src = Kz + PLK + (size_t)r * CDK + c * 8;
        cp_async16(sbase + p * QKPLANE + r * QKROWB + c * 16, src);
    }
    cp_commit();
    cp_wait<0>();
    __syncthreads();

    float acc[2][8][4];
    #pragma unroll
    for (int i = 0; i < 2; i++)
        #pragma unroll
        for (int j = 0; j < 8; j++)
            #pragma unroll
            for (int c = 0; c < 4; c++) acc[i][j][c] = 0.f;

    #pragma unroll
    for (int ks = 0; ks < 4; ks++) {
        uint32_t qf[2][4];
        #pragma unroll
        for (int tm = 0; tm < 2; tm++) {
            int row = wm * 32 + tm * 16 + lane8 + (lg & 1) * 8;
            int col = ks * 32 + (lg >> 1) * 16;
            ldm4(qf[tm], sbase + row * QKROWB + col);
        }
        #pragma unroll
        for (int tp = 0; tp < 4; tp++) {
            uint32_t kh[4], kl[4];
            int row = wn * 64 + tp * 16 + lane8 + (lg >> 1) * 8;
            int col = ks * 32 + (lg & 1) * 16;
            uint32_t addr = sbase + QKPLANE + row * QKROWB + col;
            ldm4(kh, addr);
            ldm4(kl, addr + QKPLANE);
            #pragma unroll
            for (int tm = 0; tm < 2; tm++) {
                #pragma unroll
                for (int h2 = 0; h2 < 2; h2++) {
                    float* c = acc[tm][tp * 2 + h2];
                    mma_f16(c, qf[tm], kh + h2 * 2);
                    mma_f16(c, qf[tm], kl + h2 * 2);
                }
            }
        }
    }

    const int gid = lane >> 2;
    const int tig = lane & 3;
    #pragma unroll
    for (int tm = 0; tm < 2; tm++) {
        #pragma unroll
        for (int tn = 0; tn < 8; tn++) {
            float* c = acc[tm][tn];
            const int m = m0 + wm * 32 + tm * 16 + gid;
            const int n = n0 + wn * 64 + tn * 8 + tig * 2;
            *(float2*)(Sz + (size_t)m * CS + n) =
                make_float2(c[0] * 0.125f, c[1] * 0.125f);
            *(float2*)(Sz + (size_t)(m + 8) * CS + n) =
                make_float2(c[2] * 0.125f, c[3] * 0.125f);
        }
    }
}

// ============================================================================
// Row-ops: reads fp32 scores, writes fp16 probabilities (causal-limited)
// ============================================================================
__global__ void __launch_bounds__(256) rowops_kernel(
    const float* __restrict__ scores, const float* __restrict__ gammas,
    __half* __restrict__ Pout)
{
    const long gid = blockIdx.x;
    const int  i   = (int)(gid & (CS - 1));
    const int  h   = (int)((gid >> 10) & (CH - 1));
    const float* row = scores + gid * CS;

    const int tid  = threadIdx.x;
    const int lane = tid & 31;
    const int warp = tid >> 5;
    const int jb   = tid << 2;

    __shared__ float sm[64];

    float4 sv = *(const float4*)(row + jb);
    float s0 = sv.x, s1 = sv.y, s2 = sv.z, s3 = sv.w;

    float mx = fmaxf(fmaxf(s0, s1), fmaxf(s2, s3));
    #pragma unroll
    for (int o = 16; o; o >>= 1) mx = fmaxf(mx, __shfl_xor_sync(0xffffffffu, mx, o));
    if (lane == 0) sm[warp] = mx;
    __syncthreads();
    if (tid == 0) {
        float t = sm[0];
        #pragma unroll
        for (int w = 1; w < 8; w++) t = fmaxf(t, sm[w]);
        sm[32] = t;
    }
    __syncthreads();
    const float m = sm[32];

    float e0 = __expf(s0 - m), e1 = __expf(s1 - m), e2 = __expf(s2 - m), e3 = __expf(s3 - m);
    float zl = e0 + e1 + e2 + e3;
    #pragma unroll
    for (int o = 16; o; o >>= 1) zl += __shfl_xor_sync(0xffffffffu, zl, o);
    __syncthreads();
    if (lane == 0) sm[warp] = zl;
    __syncthreads();
    if (tid == 0) { float t = 0.f; for (int w = 0; w < 8; w++) t += sm[w]; sm[33] = t; }

    float me0 = (jb + 0 <= i) ? e0 : 0.f;
    float me1 = (jb + 1 <= i) ? e1 : 0.f;
    float me2 = (jb + 2 <= i) ? e2 : 0.f;
    float me3 = (jb + 3 <= i) ? e3 : 0.f;
    float c0 = me0, c1 = c0 + me1, c2 = c1 + me2, c3 = c2 + me3;
    float x = c3;
    #pragma unroll
    for (int d = 1; d < 32; d <<= 1) {
        float y = __shfl_up_sync(0xffffffffu, x, d);
        if (lane >= d) x += y;
    }
    if (lane == 31) sm[16 + warp] = x;
    __syncthreads();
    if (tid == 0) {
        float a = 0.f;
        #pragma unroll
        for (int w = 0; w < 8; w++) { float t = sm[16 + w]; sm[24 + w] = a; a += t; }
        sm[34] = a;
    }
    __syncthreads();
    const float Z     = sm[33];
    const float T     = sm[34];
    const float carry = sm[24 + warp] + (x - c3);
    c0 += carry; c1 += carry; c2 += carry; c3 += carry;

    const float g     = gammas[h];
    const float gamma = -((g > 20.f) ? g : log1pf(__expf(g)));
    const float invZ  = 1.f / Z;
    const float NEG_INF = -__int_as_float(0x7f800000);

    float n0, n1, n2, n3;
    {
        int j;
        j = jb + 0;
        if (j <= i) {
            float d2 = fmaxf((T - c0) * invZ * (float)(i - j), 0.f);
            float eff = fminf(fmaxf(__expf(gamma * sqrtf(d2)), 1e-5f), 1e5f);
            n0 = s0 * eff;
        } else n0 = NEG_INF;
        j = jb + 1;
        if (j <= i) {
            float d2 = fmaxf((T - c1) * invZ * (float)(i - j), 0.f);
            float eff = fminf(fmaxf(__expf(gamma * sqrtf(d2)), 1e-5f), 1e5f);
            n1 = s1 * eff;
        } else n1 = NEG_INF;
        j = jb + 2;
        if (j <= i) {
            float d2 = fmaxf((T - c2) * invZ * (float)(i - j), 0.f);
            float eff = fminf(fmaxf(__expf(gamma * sqrtf(d2)), 1e-5f), 1e5f);
            n2 = s2 * eff;
        } else n2 = NEG_INF;
        j = jb + 3;
        if (j <= i) {
            float d2 = fmaxf((T - c3) * invZ * (float)(i - j), 0.f);
            float eff = fminf(fmaxf(__expf(gamma * sqrtf(d2)), 1e-5f), 1e5f);
            n3 = s3 * eff;
        } else n3 = NEG_INF;
    }

    float mx2 = fmaxf(fmaxf(n0, n1), fmaxf(n2, n3));
    #pragma unroll
    for (int o = 16; o; o >>= 1) mx2 = fmaxf(mx2, __shfl_xor_sync(0xffffffffu, mx2, o));
    __syncthreads();
    if (lane == 0) sm[warp] = mx2;
    __syncthreads();
    if (tid == 0) {
        float t = sm[0];
        #pragma unroll
        for (int w = 1; w < 8; w++) t = fmaxf(t, sm[w]);
        sm[35] = t;
    }
    __syncthreads();
    const float m2 = sm[35];

    float q0 = __expf(n0 - m2), q1 = __expf(n1 - m2), q2 = __expf(n2 - m2), q3 = __expf(n3 - m2);
    float z2 = q0 + q1 + q2 + q3;
    #pragma unroll
    for (int o = 16; o; o >>= 1) z2 += __shfl_xor_sync(0xffffffffu, z2, o);
    __syncthreads();
    if (lane == 0) sm[warp] = z2;
    __syncthreads();
    if (tid == 0) { float t = 0.f; for (int w = 0; w < 8; w++) t += sm[w]; sm[36] = t; }
    __syncthreads();
    const float invZ2 = 1.f / sm[36];

    if ((jb >> 7) <= (i >> 7)) {
        __half2 p01 = __floats2half2_rn(q0 * invZ2, q1 * invZ2);
        __half2 p23 = __floats2half2_rn(q2 * invZ2, q3 * invZ2);
        __half2* outp = (__half2*)(Pout + gid * CS + jb);
        outp[0] = p01;
        outp[1] = p23;
    }
}

// ============================================================================
// AV HMMA (triangular)
// ============================================================================
#define AROWB 144
#define AP_BYTES (128*AROWB)
#define AV_BYTES (2*64*AROWB)
#define AV_BUF (AP_BYTES + AV_BYTES)
#define AV_SMEM (2*AV_BUF)

__global__ void __launch_bounds__(256, 1) av_mma_kernel(
    const __half* __restrict__ Pg, const __half* __restrict__ Vt, long PLV,
    __nv_bfloat16* __restrict__ Cc, long PLC)
{
    extern __shared__ char smem[];
    const uint32_t sbase = smem_u32(smem);

    const int z  = blockIdx.z;
    const int m0 = blockIdx.y * 128;
    const __half* Pz = Pg + (size_t)z * CS * CS;
    const __half* Vz = Vt + (size_t)z * CDK * CS;

    const int tid  = threadIdx.x;
    const int warp = tid >> 5;
    const int lane = tid & 31;
    const int wm   = warp & 3;
    const int wn   = warp >> 2;
    const int lane8 = lane & 7;
    const int lg    = lane >> 3;

    float acc[2][4][4];
    #pragma unroll
    for (int i = 0; i < 2; i++)
        #pragma unroll
        for (int j = 0; j < 4; j++)
            #pragma unroll
            for (int c = 0; c < 4; c++) acc[i][j][c] = 0.f;

    const int nch = 2 * (blockIdx.y + 1);

    auto load_chunk = [&](int ic, int b) {
        const int k0 = ic * 64;
        #pragma unroll
        for (int i = 0; i < 8; i++) {
            int seg = i * 256 + tid;
            int part = seg >> 10;
            int r    = (seg >> 3) & 127;
            int c    = seg & 7;
            uint32_t dstb = sbase + b * AV_BUF;
            if (part == 0) {
                const __half* src = Pz + (size_t)(m0 + r) * CS + k0 + c * 8;
                cp_async16(dstb + r * AROWB + c * 16, src);
            } else {
                int pl = r >> 6, rr2 = r & 63;
                const __half* src = Vz + (size_t)pl * PLV + (size_t)rr2 * CS + k0 + c * 8;
                cp_async16(dstb + AP_BYTES + pl * (64 * AROWB) + rr2 * AROWB + c * 16, src);
            }
        }
        cp_commit();
    };

    load_chunk(0, 0);
    load_chunk(1, 1);

    for (int ic = 0; ic < nch; ic++) {
        const int b = ic & 1;
        if (ic == nch - 1) cp_wait<0>(); else cp_wait<1>();
        __syncthreads();

        const uint32_t bb = sbase + b * AV_BUF;
        #pragma unroll
        for (int kk = 0; kk < 4; kk++) {
            uint32_t af[2][4];
            #pragma unroll
            for (int tm = 0; tm < 2; tm++) {
                int row = wm * 32 + tm * 16 + lane8 + (lg & 1) * 8;
                int col = kk * 32 + (lg >> 1) * 16;
                ldm4(af[tm], bb + row * AROWB + col);
            }
            #pragma unroll
            for (int tp = 0; tp < 2; tp++) {
                uint32_t bhf[4], blf[4];
                int row = wn * 32 + tp * 16 + lane8 + (lg >> 1) * 8;
                int col = kk * 32 + (lg & 1) * 16;
                uint32_t addr = bb + AP_BYTES + row * AROWB + col;
                ldm4(bhf, addr);
                ldm4(blf, addr + 64 * AROWB);
                #pragma unroll
                for (int tm = 0; tm < 2; tm++) {
                    #pragma unroll
                    for (int h2 = 0; h2 < 2; h2++) {
                        float* c = acc[tm][tp * 2 + h2];
                        mma_f16(c, af[tm], bhf + h2 * 2);
                        mma_f16(c, af[tm], blf + h2 * 2);
                    }
                }
            }
        }
        __syncthreads();
        if (ic + 2 < nch) load_chunk(ic + 2, b);
    }

    const int gid = lane >> 2;
    const int tig = lane & 3;
    const int b_ = z >> 4;
    const int h  = z & 15;
    #pragma unroll
    for (int tm = 0; tm < 2; tm++) {
        #pragma unroll
        for (int tn = 0; tn < 4; tn++) {
            float* c = acc[tm][tn];
            const int m = m0 + wm * 32 + tm * 16 + gid;
            const int n = wn * 32 + tn * 8 + tig * 2;
            #pragma unroll
            for (int rr = 0; rr < 2; rr++) {
                const int s = m + rr * 8;
                const float va = c[rr * 2 + 0], vb = c[rr * 2 + 1];
                size_t idx = ((size_t)(b_ * CS + s)) * CDM + h * CDK + n;
                __nv_bfloat16 h2[2], l2[2];
                h2[0] = __float2bfloat16(va);
                h2[1] = __float2bfloat16(vb);
                l2[0] = __float2bfloat16(va - __bfloat162float(h2[0]));
                l2[1] = __float2bfloat16(vb - __bfloat162float(h2[1]));
                *(uint32_t*)(Cc + idx)       = *(uint32_t*)h2;
                *(uint32_t*)(Cc + PLC + idx) = *(uint32_t*)l2;
            }
        }
    }
}

// ============================================================================
// Launch sequence
// ============================================================================
extern "C" void kernel_launch(void* const* d_in, const int* in_sizes, int n_in,
                              void* d_out, int out_size)
{
    const float* q      = (const float*)d_in[0];
    const float* k      = (const float*)d_in[1];
    const float* v      = (const float*)d_in[2];
    const float* Wq     = (const float*)d_in[3];
    const float* bq     = (const float*)d_in[4];
    const float* Wk     = (const float*)d_in[5];
    const float* bk     = (const float*)d_in[6];
    const float* Wv     = (const float*)d_in[7];
    const float* bv     = (const float*)d_in[8];
    const float* Wo     = (const float*)d_in[9];
    const float* bo     = (const float*)d_in[10];
    const float* gammas = (const float*)d_in[11];
    float* out = (float*)d_out;

    float *sc;
    __half *ps, *vts, *qhs, *khs;
    __nv_bfloat16 *qs, *ks, *vs, *ccs, *wqs, *wks, *wvs, *wos;
    cudaGetSymbolAddress((void**)&sc,  g_scores);
    cudaGetSymbolAddress((void**)&ps,  g_ps);
    cudaGetSymbolAddress((void**)&vts, g_vts);
    cudaGetSymbolAddress((void**)&qhs, g_qhs);
    cudaGetSymbolAddress((void**)&khs, g_khs);
    cudaGetSymbolAddress((void**)&qs,  g_qs);
    cudaGetSymbolAddress((void**)&ks,  g_ks);
    cudaGetSymbolAddress((void**)&vs,  g_vs);
    cudaGetSymbolAddress((void**)&ccs, g_ccs);
    cudaGetSymbolAddress((void**)&wqs, g_wqs);
    cudaGetSymbolAddress((void**)&wks, g_wks);
    cudaGetSymbolAddress((void**)&wvs, g_wvs);
    cudaGetSymbolAddress((void**)&wos, g_wos);

    cudaFuncSetAttribute(proj_gemm_kernel, cudaFuncAttributeMaxDynamicSharedMemorySize, MM_SMEM);
    cudaFuncSetAttribute(out_gemm_kernel,  cudaFuncAttributeMaxDynamicSharedMemorySize, MM_SMEM);
    cudaFuncSetAttribute(qk_gemm_kernel,   cudaFuncAttributeMaxDynamicSharedMemorySize, QK_SMEM);
    cudaFuncSetAttribute(av_mma_kernel,    cudaFuncAttributeMaxDynamicSharedMemorySize, AV_SMEM);

    const int  M    = CB * CS;              // 4096
    const long nBig = (long)M * CDM;        // 4 M elems
    const long nW   = (long)CDM * CDM;      // 1 M elems
    const long nH   = (long)CBH * CS * CDK; // 4 M elems

    // one combined split launch for all 7 tensors
    SplitPack sp;
    sp.src[0] = q;  sp.dst[0] = qs;
    sp.src[1] = k;  sp.dst[1] = ks;
    sp.src[2] = v;  sp.dst[2] = vs;
    sp.src[3] = Wq; sp.dst[3] = wqs;
    sp.src[4] = Wk; sp.dst[4] = wks;
    sp.src[5] = Wv; sp.dst[5] = wvs;
    sp.src[6] = Wo; sp.dst[6] = wos;
    split_all_kernel<<<16384, 256>>>(sp);

    // one fused QKV projection launch (grid.z = 3)
    ProjPack pp;
    pp.A[0] = qs; pp.B[0] = wqs; pp.bias[0] = bq; pp.out[0] = qhs; pp.PL[0] = 0;  pp.mode[0] = 4;
    pp.A[1] = ks; pp.B[1] = wks; pp.bias[1] = bk; pp.out[1] = khs; pp.PL[1] = nH; pp.mode[1] = 5;
    pp.A[2] = vs; pp.B[2] = wvs; pp.bias[2] = bv; pp.out[2] = vts; pp.PL[2] = nH; pp.mode[2] = 3;
    proj_gemm_kernel<<<dim3(CDM/128, M/128, 3), 256, MM_SMEM>>>(pp, nBig, nW);

    // scores = Qh @ Kh^T / 8 (fp32), batched over bh
    qk_gemm_kernel<<<dim3(CS/128, CS/128, CBH), 256, QK_SMEM>>>(qhs, khs, nH, sc);

    // row ops -> fp16 P (causal-limited writes)
    rowops_kernel<<<CBH * CS, 256>>>(sc, gammas, ps);

    // AV (triangular) -> concat bf16 split planes
    av_mma_kernel<<<dim3(1, CS/128, CBH), 256, AV_SMEM>>>(ps, vts, nH, ccs, nBig);

    // output projection
    out_gemm_kernel<<<dim3(CDM/128, M/128), 256, MM_SMEM>>>(ccs, nBig, wos, nW, bo, out);
}

// round 8
// speedup vs baseline: 1.1505x; 1.1505x over previous
#include <cuda_runtime.h>
#include <cuda_bf16.h>
#include <cuda_fp16.h>
#include <math.h>
#include <stdint.h>

// Problem constants
#define CB   4
#define CS   1024
#define CDM  1024
#define CH   16
#define CDK  64
#define CBH  (CB*CH)

// ---------------- scratch (device globals: allocation-free) ----------------
__device__ float g_scores[(size_t)CBH*CS*CS];            // 256 MB fp32
__device__ __half g_ps [(size_t)CBH*CS*CS];              // 128 MB fp16 (P)
__device__ __half g_vts[2*(size_t)CBH*CDK*CS];           // V^T fp16 hi/lo
__device__ __half g_qhs[(size_t)CBH*CS*CDK];             // Q fp16 (hi only)
__device__ __half g_khs[2*(size_t)CBH*CS*CDK];           // K fp16 hi/lo
__device__ __nv_bfloat16 g_qs [2*(size_t)CB*CS*CDM];
__device__ __nv_bfloat16 g_ks [2*(size_t)CB*CS*CDM];
__device__ __nv_bfloat16 g_vs [2*(size_t)CB*CS*CDM];
__device__ __nv_bfloat16 g_ccs[2*(size_t)CB*CS*CDM];
__device__ __nv_bfloat16 g_wqs[2*(size_t)CDM*CDM];
__device__ __nv_bfloat16 g_wks[2*(size_t)CDM*CDM];
__device__ __nv_bfloat16 g_wvs[2*(size_t)CDM*CDM];
__device__ __nv_bfloat16 g_wos[2*(size_t)CDM*CDM];

// ============================================================================
// helpers
// ============================================================================
__device__ __forceinline__ uint32_t smem_u32(const void* p) {
    uint32_t a;
    asm("{ .reg .u64 t; cvta.to.shared.u64 t, %1; cvt.u32.u64 %0, t; }"
        : "=r"(a) : "l"(p));
    return a;
}
__device__ __forceinline__ void cp_async16(uint32_t dst, const void* src) {
    asm volatile("cp.async.cg.shared.global [%0], [%1], 16;"
                 :: "r"(dst), "l"(src) : "memory");
}
__device__ __forceinline__ void cp_commit() {
    asm volatile("cp.async.commit_group;" ::: "memory");
}
template<int N>
__device__ __forceinline__ void cp_wait() {
    asm volatile("cp.async.wait_group %0;" :: "n"(N) : "memory");
}
__device__ __forceinline__ void ldm4(uint32_t* r, uint32_t addr) {
    asm volatile("ldmatrix.sync.aligned.m8n8.x4.shared.b16 {%0,%1,%2,%3}, [%4];"
                 : "=r"(r[0]), "=r"(r[1]), "=r"(r[2]), "=r"(r[3]) : "r"(addr));
}
__device__ __forceinline__ void mma_bf16(float* c, const uint32_t* a, const uint32_t* b) {
    asm volatile(
        "mma.sync.aligned.m16n8k16.row.col.f32.bf16.bf16.f32 "
        "{%0,%1,%2,%3}, {%4,%5,%6,%7}, {%8,%9}, {%0,%1,%2,%3};"
        : "+f"(c[0]), "+f"(c[1]), "+f"(c[2]), "+f"(c[3])
        : "r"(a[0]), "r"(a[1]), "r"(a[2]), "r"(a[3]), "r"(b[0]), "r"(b[1]));
}
__device__ __forceinline__ void mma_f16(float* c, const uint32_t* a, const uint32_t* b) {
    asm volatile(
        "mma.sync.aligned.m16n8k16.row.col.f32.f16.f16.f32 "
        "{%0,%1,%2,%3}, {%4,%5,%6,%7}, {%8,%9}, {%0,%1,%2,%3};"
        : "+f"(c[0]), "+f"(c[1]), "+f"(c[2]), "+f"(c[3])
        : "r"(a[0]), "r"(a[1]), "r"(a[2]), "r"(a[3]), "r"(b[0]), "r"(b[1]));
}

// ============================================================================
// Split fp32 -> bf16 hi/lo planes
// ============================================================================
__global__ void split_bf16_kernel(const float* __restrict__ x,
                                  __nv_bfloat16* __restrict__ out, long n)
{
    long i = ((long)blockIdx.x * blockDim.x + threadIdx.x) * 4;
    if (i >= n) return;
    float4 v = *(const float4*)(x + i);
    float f[4] = {v.x, v.y, v.z, v.w};
    __nv_bfloat16 h[4], l[4];
    #pragma unroll
    for (int j = 0; j < 4; j++) {
        h[j] = __float2bfloat16(f[j]);
        l[j] = __float2bfloat16(f[j] - __bfloat162float(h[j]));
    }
    *(uint2*)(out + i)     = *(uint2*)h;
    *(uint2*)(out + n + i) = *(uint2*)l;
}

// ============================================================================
// HMMA GEMM (bf16-split x3 combos, fp32 accumulate)
// OUT_MODE 0: fp32 row-major [M,N]
// OUT_MODE 3: fp16 hi/lo planes, transposed head-scatter
// OUT_MODE 4: fp16 single plane, head-scatter
// OUT_MODE 5: fp16 hi/lo planes, head-scatter
// ============================================================================
#define ROWB 80
#define PLANE 10240
#define BUF   (4*PLANE)
#define MM_SMEM (2*BUF)

template<int OUT_MODE>
__global__ void __launch_bounds__(256, 1) mma_gemm_kernel(
    const __nv_bfloat16* __restrict__ A, long loA,
    const __nv_bfloat16* __restrict__ B, long loB,
    const float* __restrict__ bias, float* __restrict__ C,
    void* __restrict__ Cpl, long PL,
    int M, int N, int K, float alpha)
{
    extern __shared__ char smem[];
    const uint32_t sbase = smem_u32(smem);

    const int m0 = blockIdx.y * 128;
    const int n0 = blockIdx.x * 128;

    const int tid  = threadIdx.x;
    const int warp = tid >> 5;
    const int lane = tid & 31;
    const int wm   = warp & 3;
    const int wn   = warp >> 2;
    const int lane8 = lane & 7;
    const int lg    = lane >> 3;

    const __nv_bfloat16* bases[4];
    bases[0] = A + (size_t)m0 * K;
    bases[1] = bases[0] + loA;
    bases[2] = B + (size_t)n0 * K;
    bases[3] = bases[2] + loB;

    float acc[2][8][4];
    #pragma unroll
    for (int i = 0; i < 2; i++)
        #pragma unroll
        for (int j = 0; j < 8; j++)
            #pragma unroll
            for (int c = 0; c < 4; c++) acc[i][j][c] = 0.f;

    const int nch = K >> 5;

    auto load_chunk = [&](int ic, int b) {
        const int k0 = ic * 32;
        #pragma unroll
        for (int i = 0; i < 8; i++) {
            int seg = i * 256 + tid;
            int p   = seg >> 9;
            int r   = (seg >> 2) & 127;
            int c   = seg & 3;
            const __nv_bfloat16* src = bases[p] + (size_t)r * K + k0 + c * 8;
            uint32_t dst = sbase + b * BUF + p * PLANE + r * ROWB + c * 16;
            cp_async16(dst, src);
        }
        cp_commit();
    };

    load_chunk(0, 0);
    if (nch > 1) load_chunk(1, 1);

    for (int ic = 0; ic < nch; ic++) {
        const int b = ic & 1;
        if (ic == nch - 1) cp_wait<0>(); else cp_wait<1>();
        __syncthreads();

        const uint32_t bb = sbase + b * BUF;
        #pragma unroll
        for (int kk = 0; kk < 2; kk++) {
            uint32_t ah[2][4], al[2][4];
            #pragma unroll
            for (int tm = 0; tm < 2; tm++) {
                int row = wm * 32 + tm * 16 + lane8 + (lg & 1) * 8;
                int col = kk * 32 + (lg >> 1) * 16;
                uint32_t addr = bb + row * ROWB + col;
                ldm4(ah[tm], addr);
                ldm4(al[tm], addr + PLANE);
            }
            #pragma unroll
            for (int tp = 0; tp < 4; tp++) {
                uint32_t bhf[4], blf[4];
                int row = wn * 64 + tp * 16 + lane8 + (lg >> 1) * 8;
                int col = kk * 32 + (lg & 1) * 16;
                uint32_t addr = bb + 2 * PLANE + row * ROWB + col;
                ldm4(bhf, addr);
                ldm4(blf, addr + PLANE);
                #pragma unroll
                for (int tm = 0; tm < 2; tm++) {
                    #pragma unroll
                    for (int h2 = 0; h2 < 2; h2++) {
                        float* c = acc[tm][tp * 2 + h2];
                        mma_bf16(c, ah[tm], bhf + h2 * 2);
                        mma_bf16(c, ah[tm], blf + h2 * 2);
                        mma_bf16(c, al[tm], bhf + h2 * 2);
                    }
                }
            }
        }
        __syncthreads();
        if (ic + 2 < nch) load_chunk(ic + 2, b);
    }

    // ---- epilogue ----
    const int gid = lane >> 2;
    const int tig = lane & 3;
    #pragma unroll
    for (int tm = 0; tm < 2; tm++) {
        #pragma unroll
        for (int tn = 0; tn < 8; tn++) {
            float* c = acc[tm][tn];
            const int m = m0 + wm * 32 + tm * 16 + gid;
            const int n = n0 + wn * 64 + tn * 8 + tig * 2;
            float b0 = 0.f, b1 = 0.f;
            if (bias) { b0 = bias[n]; b1 = bias[n + 1]; }
            float v00 = c[0] * alpha + b0, v01 = c[1] * alpha + b1;
            float v10 = c[2] * alpha + b0, v11 = c[3] * alpha + b1;
            if (OUT_MODE == 0) {
                *(float2*)(C + (size_t)m * N + n)       = make_float2(v00, v01);
                *(float2*)(C + (size_t)(m + 8) * N + n) = make_float2(v10, v11);
            } else if (OUT_MODE == 3) { // fp16 transposed planes
                __half* P = (__half*)Cpl;
                const int h  = n >> 6;
                const int dk = n & 63;
                #pragma unroll
                for (int rr = 0; rr < 2; rr++) {
                    const int mm = m + rr * 8;
                    const float va = rr ? v10 : v00, vb = rr ? v11 : v01;
                    const int b_ = mm >> 10, s = mm & 1023;
                    size_t base = (((size_t)(b_ * CH + h)) * CDK + dk) * CS + s;
                    __half ha = __float2half(va);
                    __half la = __float2half(va - __half2float(ha));
                    __half hb = __float2half(vb);
                    __half lb = __float2half(vb - __half2float(hb));
                    P[base]           = ha;
                    P[base + PL]      = la;
                    P[base + CS]      = hb;
                    P[base + CS + PL] = lb;
                }
            } else { // OUT_MODE 4/5: fp16 plane(s), head-scatter row-major
                __half* P = (__half*)Cpl;
                const int h  = n >> 6;
                const int dk = n & 63;
                #pragma unroll
                for (int rr = 0; rr < 2; rr++) {
                    const int mm = m + rr * 8;
                    const float va = rr ? v10 : v00, vb = rr ? v11 : v01;
                    const int b_ = mm >> 10, s = mm & 1023;
                    size_t idx = (((size_t)(b_ * CH + h)) * CS + s) * CDK + dk;
                    __half ha = __float2half(va);
                    __half hb = __float2half(vb);
                    __half2 hp = __halves2half2(ha, hb);
                    *(uint32_t*)(P + idx) = *(uint32_t*)&hp;
                    if (OUT_MODE == 5) {
                        __half la = __float2half(va - __half2float(ha));
                        __half lb = __float2half(vb - __half2float(hb));
                        __half2 lp = __halves2half2(la, lb);
                        *(uint32_t*)(P + PL + idx) = *(uint32_t*)&lp;
                    }
                }
            }
        }
    }
}

// ============================================================================
// QK^T scores kernel (fp16 Q hi x K hi/lo, 2 combos, K=64 single shot)
// ============================================================================
#define QKROWB 144
#define QKPLANE (128*QKROWB)
#define QK_SMEM (3*QKPLANE)

__global__ void __launch_bounds__(256, 1) qk_gemm_kernel(
    const __half* __restrict__ Qg,
    const __half* __restrict__ Kg, long PLK,
    float* __restrict__ S)
{
    extern __shared__ char smem[];
    const uint32_t sbase = smem_u32(smem);

    const int z  = blockIdx.z;
    const int m0 = blockIdx.y * 128;
    const int n0 = blockIdx.x * 128;
    const __half* Qz = Qg + ((size_t)z * CS + m0) * CDK;
    const __half* Kz = Kg + ((size_t)z * CS + n0) * CDK;
    float* Sz = S + (size_t)z * CS * CS;

    const int tid  = threadIdx.x;
    const int warp = tid >> 5;
    const int lane = tid & 31;
    const int wm   = warp & 3;
    const int wn   = warp >> 2;
    const int lane8 = lane & 7;
    const int lg    = lane >> 3;

    #pragma unroll
    for (int i = 0; i < 12; i++) {
        int seg = i * 256 + tid;
        int p   = seg >> 10;
        int r   = (seg >> 3) & 127;
        int c   = seg & 7;
        const __half* src;
        if (p == 0)      src = Qz + (size_t)r * CDK + c * 8;
        else if (p == 1) src = Kz + (size_t)r * CDK + c * 8;
        else             src = Kz + PLK + (size_t)r * CDK + c * 8;
        cp_async16(sbase + p * QKPLANE + r * QKROWB + c * 16, src);
    }
    cp_commit();
    cp_wait<0>();
    __syncthreads();

    float acc[2][8][4];
    #pragma unroll
    for (int i = 0; i < 2; i++)
        #pragma unroll
        for (int j = 0; j < 8; j++)
            #pragma unroll
            for (int c = 0; c < 4; c++) acc[i][j][c] = 0.f;

    #pragma unroll
    for (int ks = 0; ks < 4; ks++) {
        uint32_t qf[2][4];
        #pragma unroll
        for (int tm = 0; tm < 2; tm++) {
            int row = wm * 32 + tm * 16 + lane8 + (lg & 1) * 8;
            int col = ks * 32 + (lg >> 1) * 16;
            ldm4(qf[tm], sbase + row * QKROWB + col);
        }
        #pragma unroll
        for (int tp = 0; tp < 4; tp++) {
            uint32_t kh[4], kl[4];
            int row = wn * 64 + tp * 16 + lane8 + (lg >> 1) * 8;
            int col = ks * 32 + (lg & 1) * 16;
            uint32_t addr = sbase + QKPLANE + row * QKROWB + col;
            ldm4(kh, addr);
            ldm4(kl, addr + QKPLANE);
            #pragma unroll
            for (int tm = 0; tm < 2; tm++) {
                #pragma unroll
                for (int h2 = 0; h2 < 2; h2++) {
                    float* c = acc[tm][tp * 2 + h2];
                    mma_f16(c, qf[tm], kh + h2 * 2);
                    mma_f16(c, qf[tm], kl + h2 * 2);
                }
            }
        }
    }

    const int gid = lane >> 2;
    const int tig = lane & 3;
    #pragma unroll
    for (int tm = 0; tm < 2; tm++) {
        #pragma unroll
        for (int tn = 0; tn < 8; tn++) {
            float* c = acc[tm][tn];
            const int m = m0 + wm * 32 + tm * 16 + gid;
            const int n = n0 + wn * 64 + tn * 8 + tig * 2;
            *(float2*)(Sz + (size_t)m * CS + n) =
                make_float2(c[0] * 0.125f, c[1] * 0.125f);
            *(float2*)(Sz + (size_t)(m + 8) * CS + n) =
                make_float2(c[2] * 0.125f, c[3] * 0.125f);
        }
    }
}

// ============================================================================
// Row-ops v2: warp per row, no barriers, no smem.
// 8 rows per CTA (256 threads). Each thread holds 32 row elements in regs.
// Causal group limit glim = i>>7 is warp-uniform -> heavy work (cumsum,
// decay, second softmax, P writes) runs only on groups 0..glim.
// ============================================================================
__global__ void __launch_bounds__(256) rowops_kernel(
    const float* __restrict__ scores, const float* __restrict__ gammas,
    __half* __restrict__ Pout)
{
    const long gid = (long)blockIdx.x * 8 + (threadIdx.x >> 5);
    const int lane = threadIdx.x & 31;
    const int i = (int)(gid & (CS - 1));
    const int h = (int)((gid >> 10) & (CH - 1));
    const float* row = scores + gid * CS;

    float s[32];
    #pragma unroll
    for (int g = 0; g < 8; g++)
        *(float4*)(s + g * 4) = *(const float4*)(row + g * 128 + lane * 4);

    // ---- 1) max over full (unmasked) row ----
    float mx = s[0];
    #pragma unroll
    for (int q = 1; q < 32; q++) mx = fmaxf(mx, s[q]);
    #pragma unroll
    for (int o = 16; o; o >>= 1) mx = fmaxf(mx, __shfl_xor_sync(0xffffffffu, mx, o));

    // ---- 2) exp + full sum ----
    float e[32];
    float zl = 0.f;
    #pragma unroll
    for (int q = 0; q < 32; q++) { e[q] = __expf(s[q] - mx); zl += e[q]; }
    #pragma unroll
    for (int o = 16; o; o >>= 1) zl += __shfl_xor_sync(0xffffffffu, zl, o);
    const float invZ = 1.f / zl;

    const int glim = i >> 7;          // warp-uniform causal group limit

    // ---- 3) masked inclusive cumsum over groups 0..glim (into e) ----
    float carry = 0.f;
    #pragma unroll
    for (int g = 0; g < 8; g++) {
        if (g <= glim) {
            const int j0 = g * 128 + lane * 4;
            float m0 = (j0 + 0 <= i) ? e[g*4+0] : 0.f;
            float m1 = (j0 + 1 <= i) ? e[g*4+1] : 0.f;
            float m2 = (j0 + 2 <= i) ? e[g*4+2] : 0.f;
            float m3 = (j0 + 3 <= i) ? e[g*4+3] : 0.f;
            float l0 = m0, l1 = l0 + m1, l2 = l1 + m2, l3 = l2 + m3;
            float x = l3;
            #pragma unroll
            for (int d = 1; d < 32; d <<= 1) {
                float y = __shfl_up_sync(0xffffffffu, x, d);
                if (lane >= d) x += y;
            }
            float excl = x - l3;
            float tot  = __shfl_sync(0xffffffffu, x, 31);
            e[g*4+0] = carry + excl + l0;
            e[g*4+1] = carry + excl + l1;
            e[g*4+2] = carry + excl + l2;
            e[g*4+3] = carry + excl + l3;
            carry += tot;
        }
    }
    const float T = carry;

    // ---- 4) decay + mask (into s), groups 0..glim only ----
    const float g_  = gammas[h];
    const float gamma = -((g_ > 20.f) ? g_ : log1pf(__expf(g_)));
    const float NEG_INF = -__int_as_float(0x7f800000);
    #pragma unroll
    for (int g = 0; g < 8; g++) {
        if (g <= glim) {
            const int j0 = g * 128 + lane * 4;
            #pragma unroll
            for (int q = 0; q < 4; q++) {
                const int j = j0 + q;
                if (j <= i) {
                    float d2 = fmaxf((T - e[g*4+q]) * invZ * (float)(i - j), 0.f);
                    float eff = fminf(fmaxf(__expf(gamma * sqrtf(d2)), 1e-5f), 1e5f);
                    s[g*4+q] = s[g*4+q] * eff;
                } else {
                    s[g*4+q] = NEG_INF;
                }
            }
        }
    }

    // ---- 5) second (masked) softmax over groups 0..glim ----
    float mx2 = NEG_INF;
    #pragma unroll
    for (int g = 0; g < 8; g++)
        if (g <= glim) {
            #pragma unroll
            for (int q = 0; q < 4; q++) mx2 = fmaxf(mx2, s[g*4+q]);
        }
    #pragma unroll
    for (int o = 16; o; o >>= 1) mx2 = fmaxf(mx2, __shfl_xor_sync(0xffffffffu, mx2, o));

    float z2 = 0.f;
    #pragma unroll
    for (int g = 0; g < 8; g++)
        if (g <= glim) {
            #pragma unroll
            for (int q = 0; q < 4; q++) {
                s[g*4+q] = __expf(s[g*4+q] - mx2);
                z2 += s[g*4+q];
            }
        }
    #pragma unroll
    for (int o = 16; o; o >>= 1) z2 += __shfl_xor_sync(0xffffffffu, z2, o);
    const float invZ2 = 1.f / z2;

    // ---- 6) write P (fp16) for groups 0..glim (AV reads exactly these) ----
    __half* prow = Pout + gid * CS;
    #pragma unroll
    for (int g = 0; g < 8; g++) {
        if (g <= glim) {
            __half2 p0 = __floats2half2_rn(s[g*4+0] * invZ2, s[g*4+1] * invZ2);
            __half2 p1 = __floats2half2_rn(s[g*4+2] * invZ2, s[g*4+3] * invZ2);
            uint2 pk;
            pk.x = *(uint32_t*)&p0;
            pk.y = *(uint32_t*)&p1;
            *(uint2*)(prow + g * 128 + lane * 4) = pk;
        }
    }
}

// ============================================================================
// AV HMMA (triangular)
// ============================================================================
#define AROWB 144
#define AP_BYTES (128*AROWB)
#define AV_BYTES (2*64*AROWB)
#define AV_BUF (AP_BYTES + AV_BYTES)
#define AV_SMEM (2*AV_BUF)

__global__ void __launch_bounds__(256, 1) av_mma_kernel(
    const __half* __restrict__ Pg, const __half* __restrict__ Vt, long PLV,
    __nv_bfloat16* __restrict__ Cc, long PLC)
{
    extern __shared__ char smem[];
    const uint32_t sbase = smem_u32(smem);

    const int z  = blockIdx.z;
    const int m0 = blockIdx.y * 128;
    const __half* Pz = Pg + (size_t)z * CS * CS;
    const __half* Vz = Vt + (size_t)z * CDK * CS;

    const int tid  = threadIdx.x;
    const int warp = tid >> 5;
    const int lane = tid & 31;
    const int wm   = warp & 3;
    const int wn   = warp >> 2;
    const int lane8 = lane & 7;
    const int lg    = lane >> 3;

    float acc[2][4][4];
    #pragma unroll
    for (int i = 0; i < 2; i++)
        #pragma unroll
        for (int j = 0; j < 4; j++)
            #pragma unroll
            for (int c = 0; c < 4; c++) acc[i][j][c] = 0.f;

    const int nch = 2 * (blockIdx.y + 1);

    auto load_chunk = [&](int ic, int b) {
        const int k0 = ic * 64;
        #pragma unroll
        for (int i = 0; i < 8; i++) {
            int seg = i * 256 + tid;
            int part = seg >> 10;
            int r    = (seg >> 3) & 127;
            int c    = seg & 7;
            uint32_t dstb = sbase + b * AV_BUF;
            if (part == 0) {
                const __half* src = Pz + (size_t)(m0 + r) * CS + k0 + c * 8;
                cp_async16(dstb + r * AROWB + c * 16, src);
            } else {
                int pl = r >> 6, rr2 = r & 63;
                const __half* src = Vz + (size_t)pl * PLV + (size_t)rr2 * CS + k0 + c * 8;
                cp_async16(dstb + AP_BYTES + pl * (64 * AROWB) + rr2 * AROWB + c * 16, src);
            }
        }
        cp_commit();
    };

    load_chunk(0, 0);
    load_chunk(1, 1);

    for (int ic = 0; ic < nch; ic++) {
        const int b = ic & 1;
        if (ic == nch - 1) cp_wait<0>(); else cp_wait<1>();
        __syncthreads();

        const uint32_t bb = sbase + b * AV_BUF;
        #pragma unroll
        for (int kk = 0; kk < 4; kk++) {
            uint32_t af[2][4];
            #pragma unroll
            for (int tm = 0; tm < 2; tm++) {
                int row = wm * 32 + tm * 16 + lane8 + (lg & 1) * 8;
                int col = kk * 32 + (lg >> 1) * 16;
                ldm4(af[tm], bb + row * AROWB + col);
            }
            #pragma unroll
            for (int tp = 0; tp < 2; tp++) {
                uint32_t bhf[4], blf[4];
                int row = wn * 32 + tp * 16 + lane8 + (lg >> 1) * 8;
                int col = kk * 32 + (lg & 1) * 16;
                uint32_t addr = bb + AP_BYTES + row * AROWB + col;
                ldm4(bhf, addr);
                ldm4(blf, addr + 64 * AROWB);
                #pragma unroll
                for (int tm = 0; tm < 2; tm++) {
                    #pragma unroll
                    for (int h2 = 0; h2 < 2; h2++) {
                        float* c = acc[tm][tp * 2 + h2];
                        mma_f16(c, af[tm], bhf + h2 * 2);
                        mma_f16(c, af[tm], blf + h2 * 2);
                    }
                }
            }
        }
        __syncthreads();
        if (ic + 2 < nch) load_chunk(ic + 2, b);
    }

    const int gid = lane >> 2;
    const int tig = lane & 3;
    const int b_ = z >> 4;
    const int h  = z & 15;
    #pragma unroll
    for (int tm = 0; tm < 2; tm++) {
        #pragma unroll
        for (int tn = 0; tn < 4; tn++) {
            float* c = acc[tm][tn];
            const int m = m0 + wm * 32 + tm * 16 + gid;
            const int n = wn * 32 + tn * 8 + tig * 2;
            #pragma unroll
            for (int rr = 0; rr < 2; rr++) {
                const int s = m + rr * 8;
                const float va = c[rr * 2 + 0], vb = c[rr * 2 + 1];
                size_t idx = ((size_t)(b_ * CS + s)) * CDM + h * CDK + n;
                __nv_bfloat16 h2[2], l2[2];
                h2[0] = __float2bfloat16(va);
                h2[1] = __float2bfloat16(vb);
                l2[0] = __float2bfloat16(va - __bfloat162float(h2[0]));
                l2[1] = __float2bfloat16(vb - __bfloat162float(h2[1]));
                *(uint32_t*)(Cc + idx)       = *(uint32_t*)h2;
                *(uint32_t*)(Cc + PLC + idx) = *(uint32_t*)l2;
            }
        }
    }
}

// ============================================================================
// Launch sequence (R6 structure: separate splits + separate projections)
// ============================================================================
extern "C" void kernel_launch(void* const* d_in, const int* in_sizes, int n_in,
                              void* d_out, int out_size)
{
    const float* q      = (const float*)d_in[0];
    const float* k      = (const float*)d_in[1];
    const float* v      = (const float*)d_in[2];
    const float* Wq     = (const float*)d_in[3];
    const float* bq     = (const float*)d_in[4];
    const float* Wk     = (const float*)d_in[5];
    const float* bk     = (const float*)d_in[6];
    const float* Wv     = (const float*)d_in[7];
    const float* bv     = (const float*)d_in[8];
    const float* Wo     = (const float*)d_in[9];
    const float* bo     = (const float*)d_in[10];
    const float* gammas = (const float*)d_in[11];
    float* out = (float*)d_out;

    float *sc;
    __half *ps, *vts, *qhs, *khs;
    __nv_bfloat16 *qs, *ks, *vs, *ccs, *wqs, *wks, *wvs, *wos;
    cudaGetSymbolAddress((void**)&sc,  g_scores);
    cudaGetSymbolAddress((void**)&ps,  g_ps);
    cudaGetSymbolAddress((void**)&vts, g_vts);
    cudaGetSymbolAddress((void**)&qhs, g_qhs);
    cudaGetSymbolAddress((void**)&khs, g_khs);
    cudaGetSymbolAddress((void**)&qs,  g_qs);
    cudaGetSymbolAddress((void**)&ks,  g_ks);
    cudaGetSymbolAddress((void**)&vs,  g_vs);
    cudaGetSymbolAddress((void**)&ccs, g_ccs);
    cudaGetSymbolAddress((void**)&wqs, g_wqs);
    cudaGetSymbolAddress((void**)&wks, g_wks);
    cudaGetSymbolAddress((void**)&wvs, g_wvs);
    cudaGetSymbolAddress((void**)&wos, g_wos);

    cudaFuncSetAttribute(mma_gemm_kernel<0>, cudaFuncAttributeMaxDynamicSharedMemorySize, MM_SMEM);
    cudaFuncSetAttribute(mma_gemm_kernel<3>, cudaFuncAttributeMaxDynamicSharedMemorySize, MM_SMEM);
    cudaFuncSetAttribute(mma_gemm_kernel<4>, cudaFuncAttributeMaxDynamicSharedMemorySize, MM_SMEM);
    cudaFuncSetAttribute(mma_gemm_kernel<5>, cudaFuncAttributeMaxDynamicSharedMemorySize, MM_SMEM);
    cudaFuncSetAttribute(qk_gemm_kernel,   cudaFuncAttributeMaxDynamicSharedMemorySize, QK_SMEM);
    cudaFuncSetAttribute(av_mma_kernel,    cudaFuncAttributeMaxDynamicSharedMemorySize, AV_SMEM);

    const int  M    = CB * CS;              // 4096
    const long nBig = (long)M * CDM;        // 4 M elems
    const long nW   = (long)CDM * CDM;      // 1 M elems
    const long nH   = (long)CBH * CS * CDK; // 4 M elems

    // split inputs + weights to bf16 hi/lo planes
    split_bf16_kernel<<<(unsigned)(nBig/1024), 256>>>(q,  qs,  nBig);
    split_bf16_kernel<<<(unsigned)(nBig/1024), 256>>>(k,  ks,  nBig);
    split_bf16_kernel<<<(unsigned)(nBig/1024), 256>>>(v,  vs,  nBig);
    split_bf16_kernel<<<(unsigned)(nW/1024),   256>>>(Wq, wqs, nW);
    split_bf16_kernel<<<(unsigned)(nW/1024),   256>>>(Wk, wks, nW);
    split_bf16_kernel<<<(unsigned)(nW/1024),   256>>>(Wv, wvs, nW);
    split_bf16_kernel<<<(unsigned)(nW/1024),   256>>>(Wo, wos, nW);

    // Q -> fp16 single plane; K -> fp16 hi/lo planes (head-scattered)
    mma_gemm_kernel<4><<<dim3(CDM/128, M/128), 256, MM_SMEM>>>(
        qs, nBig, wqs, nW, bq, nullptr, qhs, 0, M, CDM, CDM, 1.f);
    mma_gemm_kernel<5><<<dim3(CDM/128, M/128), 256, MM_SMEM>>>(
        ks, nBig, wks, nW, bk, nullptr, khs, nH, M, CDM, CDM, 1.f);
    // V -> fp16 split planes, transposed per head
    mma_gemm_kernel<3><<<dim3(CDM/128, M/128), 256, MM_SMEM>>>(
        vs, nBig, wvs, nW, bv, nullptr, vts, nH, M, CDM, CDM, 1.f);

    // scores = Qh @ Kh^T / 8 (fp32), batched over bh
    qk_gemm_kernel<<<dim3(CS/128, CS/128, CBH), 256, QK_SMEM>>>(qhs, khs, nH, sc);

    // row ops (warp per row) -> fp16 P (causal-limited writes)
    rowops_kernel<<<CBH * CS / 8, 256>>>(sc, gammas, ps);

    // AV (triangular) -> concat bf16 split planes
    av_mma_kernel<<<dim3(1, CS/128, CBH), 256, AV_SMEM>>>(ps, vts, nH, ccs, nBig);

    // output projection
    mma_gemm_kernel<0><<<dim3(CDM/128, M/128), 256, MM_SMEM>>>(
        ccs, nBig, wos, nW, bo, out, nullptr, 0, M, CDM, CDM, 1.f);
}

// round 9
// speedup vs baseline: 1.2449x; 1.0821x over previous
#include <cuda_runtime.h>
#include <cuda_bf16.h>
#include <cuda_fp16.h>
#include <math.h>
#include <stdint.h>

// Problem constants
#define CB   4
#define CS   1024
#define CDM  1024
#define CH   16
#define CDK  64
#define CBH  (CB*CH)

// ---------------- scratch (device globals: allocation-free) ----------------
__device__ float g_scores[(size_t)CBH*CS*CS];            // 256 MB fp32
__device__ __half g_ps [(size_t)CBH*CS*CS];              // 128 MB fp16 (P)
__device__ __half g_vts[2*(size_t)CBH*CDK*CS];           // V^T fp16 hi/lo
__device__ __half g_qhs[(size_t)CBH*CS*CDK];             // Q fp16 (hi only)
__device__ __half g_khs[2*(size_t)CBH*CS*CDK];           // K fp16 hi/lo
__device__ __nv_bfloat16 g_qs [2*(size_t)CB*CS*CDM];
__device__ __nv_bfloat16 g_ks [2*(size_t)CB*CS*CDM];
__device__ __nv_bfloat16 g_vs [2*(size_t)CB*CS*CDM];
__device__ __nv_bfloat16 g_ccs[2*(size_t)CB*CS*CDM];
__device__ __nv_bfloat16 g_wqs[2*(size_t)CDM*CDM];
__device__ __nv_bfloat16 g_wks[2*(size_t)CDM*CDM];
__device__ __nv_bfloat16 g_wvs[2*(size_t)CDM*CDM];
__device__ __nv_bfloat16 g_wos[2*(size_t)CDM*CDM];

// ============================================================================
// helpers
// ============================================================================
__device__ __forceinline__ uint32_t smem_u32(const void* p) {
    uint32_t a;
    asm("{ .reg .u64 t; cvta.to.shared.u64 t, %1; cvt.u32.u64 %0, t; }"
        : "=r"(a) : "l"(p));
    return a;
}
__device__ __forceinline__ void cp_async16(uint32_t dst, const void* src) {
    asm volatile("cp.async.cg.shared.global [%0], [%1], 16;"
                 :: "r"(dst), "l"(src) : "memory");
}
__device__ __forceinline__ void cp_commit() {
    asm volatile("cp.async.commit_group;" ::: "memory");
}
template<int N>
__device__ __forceinline__ void cp_wait() {
    asm volatile("cp.async.wait_group %0;" :: "n"(N) : "memory");
}
__device__ __forceinline__ void ldm4(uint32_t* r, uint32_t addr) {
    asm volatile("ldmatrix.sync.aligned.m8n8.x4.shared.b16 {%0,%1,%2,%3}, [%4];"
                 : "=r"(r[0]), "=r"(r[1]), "=r"(r[2]), "=r"(r[3]) : "r"(addr));
}
__device__ __forceinline__ void mma_bf16(float* c, const uint32_t* a, const uint32_t* b) {
    asm volatile(
        "mma.sync.aligned.m16n8k16.row.col.f32.bf16.bf16.f32 "
        "{%0,%1,%2,%3}, {%4,%5,%6,%7}, {%8,%9}, {%0,%1,%2,%3};"
        : "+f"(c[0]), "+f"(c[1]), "+f"(c[2]), "+f"(c[3])
        : "r"(a[0]), "r"(a[1]), "r"(a[2]), "r"(a[3]), "r"(b[0]), "r"(b[1]));
}
__device__ __forceinline__ void mma_f16(float* c, const uint32_t* a, const uint32_t* b) {
    asm volatile(
        "mma.sync.aligned.m16n8k16.row.col.f32.f16.f16.f32 "
        "{%0,%1,%2,%3}, {%4,%5,%6,%7}, {%8,%9}, {%0,%1,%2,%3};"
        : "+f"(c[0]), "+f"(c[1]), "+f"(c[2]), "+f"(c[3])
        : "r"(a[0]), "r"(a[1]), "r"(a[2]), "r"(a[3]), "r"(b[0]), "r"(b[1]));
}

// ============================================================================
// Split fp32 -> bf16 hi/lo planes
// ============================================================================
__global__ void split_bf16_kernel(const float* __restrict__ x,
                                  __nv_bfloat16* __restrict__ out, long n)
{
    long i = ((long)blockIdx.x * blockDim.x + threadIdx.x) * 4;
    if (i >= n) return;
    float4 v = *(const float4*)(x + i);
    float f[4] = {v.x, v.y, v.z, v.w};
    __nv_bfloat16 h[4], l[4];
    #pragma unroll
    for (int j = 0; j < 4; j++) {
        h[j] = __float2bfloat16(f[j]);
        l[j] = __float2bfloat16(f[j] - __bfloat162float(h[j]));
    }
    *(uint2*)(out + i)     = *(uint2*)h;
    *(uint2*)(out + n + i) = *(uint2*)l;
}

// ============================================================================
// HMMA GEMM (bf16-split x3 combos, fp32 accumulate)
// OUT_MODE 0: fp32 row-major [M,N]
// OUT_MODE 3: fp16 hi/lo planes, transposed head-scatter
// OUT_MODE 4: fp16 single plane, head-scatter
// OUT_MODE 5: fp16 hi/lo planes, head-scatter
// 2 CTAs/SM target (128-reg cap via launch bounds; smem 2x80KB fits 228KB).
// ============================================================================
#define ROWB 80
#define PLANE 10240
#define BUF   (4*PLANE)
#define MM_SMEM (2*BUF)

template<int OUT_MODE>
__global__ void __launch_bounds__(256, 2) mma_gemm_kernel(
    const __nv_bfloat16* __restrict__ A, long loA,
    const __nv_bfloat16* __restrict__ B, long loB,
    const float* __restrict__ bias, float* __restrict__ C,
    void* __restrict__ Cpl, long PL,
    int M, int N, int K, float alpha)
{
    extern __shared__ char smem[];
    const uint32_t sbase = smem_u32(smem);

    const int m0 = blockIdx.y * 128;
    const int n0 = blockIdx.x * 128;

    const int tid  = threadIdx.x;
    const int warp = tid >> 5;
    const int lane = tid & 31;
    const int wm   = warp & 3;
    const int wn   = warp >> 2;
    const int lane8 = lane & 7;
    const int lg    = lane >> 3;

    const __nv_bfloat16* bases[4];
    bases[0] = A + (size_t)m0 * K;
    bases[1] = bases[0] + loA;
    bases[2] = B + (size_t)n0 * K;
    bases[3] = bases[2] + loB;

    float acc[2][8][4];
    #pragma unroll
    for (int i = 0; i < 2; i++)
        #pragma unroll
        for (int j = 0; j < 8; j++)
            #pragma unroll
            for (int c = 0; c < 4; c++) acc[i][j][c] = 0.f;

    const int nch = K >> 5;

    auto load_chunk = [&](int ic, int b) {
        const int k0 = ic * 32;
        #pragma unroll
        for (int i = 0; i < 8; i++) {
            int seg = i * 256 + tid;
            int p   = seg >> 9;
            int r   = (seg >> 2) & 127;
            int c   = seg & 3;
            const __nv_bfloat16* src = bases[p] + (size_t)r * K + k0 + c * 8;
            uint32_t dst = sbase + b * BUF + p * PLANE + r * ROWB + c * 16;
            cp_async16(dst, src);
        }
        cp_commit();
    };

    load_chunk(0, 0);
    if (nch > 1) load_chunk(1, 1);

    for (int ic = 0; ic < nch; ic++) {
        const int b = ic & 1;
        if (ic == nch - 1) cp_wait<0>(); else cp_wait<1>();
        __syncthreads();

        const uint32_t bb = sbase + b * BUF;
        #pragma unroll
        for (int kk = 0; kk < 2; kk++) {
            uint32_t ah[2][4], al[2][4];
            #pragma unroll
            for (int tm = 0; tm < 2; tm++) {
                int row = wm * 32 + tm * 16 + lane8 + (lg & 1) * 8;
                int col = kk * 32 + (lg >> 1) * 16;
                uint32_t addr = bb + row * ROWB + col;
                ldm4(ah[tm], addr);
                ldm4(al[tm], addr + PLANE);
            }
            #pragma unroll
            for (int tp = 0; tp < 4; tp++) {
                uint32_t bhf[4], blf[4];
                int row = wn * 64 + tp * 16 + lane8 + (lg >> 1) * 8;
                int col = kk * 32 + (lg & 1) * 16;
                uint32_t addr = bb + 2 * PLANE + row * ROWB + col;
                ldm4(bhf, addr);
                ldm4(blf, addr + PLANE);
                #pragma unroll
                for (int tm = 0; tm < 2; tm++) {
                    #pragma unroll
                    for (int h2 = 0; h2 < 2; h2++) {
                        float* c = acc[tm][tp * 2 + h2];
                        mma_bf16(c, ah[tm], bhf + h2 * 2);
                        mma_bf16(c, ah[tm], blf + h2 * 2);
                        mma_bf16(c, al[tm], bhf + h2 * 2);
                    }
                }
            }
        }
        __syncthreads();
        if (ic + 2 < nch) load_chunk(ic + 2, b);
    }

    // ---- epilogue ----
    const int gid = lane >> 2;
    const int tig = lane & 3;
    #pragma unroll
    for (int tm = 0; tm < 2; tm++) {
        #pragma unroll
        for (int tn = 0; tn < 8; tn++) {
            float* c = acc[tm][tn];
            const int m = m0 + wm * 32 + tm * 16 + gid;
            const int n = n0 + wn * 64 + tn * 8 + tig * 2;
            float b0 = 0.f, b1 = 0.f;
            if (bias) { b0 = bias[n]; b1 = bias[n + 1]; }
            float v00 = c[0] * alpha + b0, v01 = c[1] * alpha + b1;
            float v10 = c[2] * alpha + b0, v11 = c[3] * alpha + b1;
            if (OUT_MODE == 0) {
                *(float2*)(C + (size_t)m * N + n)       = make_float2(v00, v01);
                *(float2*)(C + (size_t)(m + 8) * N + n) = make_float2(v10, v11);
            } else if (OUT_MODE == 3) { // fp16 transposed planes
                __half* P = (__half*)Cpl;
                const int h  = n >> 6;
                const int dk = n & 63;
                #pragma unroll
                for (int rr = 0; rr < 2; rr++) {
                    const int mm = m + rr * 8;
                    const float va = rr ? v10 : v00, vb = rr ? v11 : v01;
                    const int b_ = mm >> 10, s = mm & 1023;
                    size_t base = (((size_t)(b_ * CH + h)) * CDK + dk) * CS + s;
                    __half ha = __float2half(va);
                    __half la = __float2half(va - __half2float(ha));
                    __half hb = __float2half(vb);
                    __half lb = __float2half(vb - __half2float(hb));
                    P[base]           = ha;
                    P[base + PL]      = la;
                    P[base + CS]      = hb;
                    P[base + CS + PL] = lb;
                }
            } else { // OUT_MODE 4/5: fp16 plane(s), head-scatter row-major
                __half* P = (__half*)Cpl;
                const int h  = n >> 6;
                const int dk = n & 63;
                #pragma unroll
                for (int rr = 0; rr < 2; rr++) {
                    const int mm = m + rr * 8;
                    const float va = rr ? v10 : v00, vb = rr ? v11 : v01;
                    const int b_ = mm >> 10, s = mm & 1023;
                    size_t idx = (((size_t)(b_ * CH + h)) * CS + s) * CDK + dk;
                    __half ha = __float2half(va);
                    __half hb = __float2half(vb);
                    __half2 hp = __halves2half2(ha, hb);
                    *(uint32_t*)(P + idx) = *(uint32_t*)&hp;
                    if (OUT_MODE == 5) {
                        __half la = __float2half(va - __half2float(ha));
                        __half lb = __float2half(vb - __half2float(hb));
                        __half2 lp = __halves2half2(la, lb);
                        *(uint32_t*)(P + PL + idx) = *(uint32_t*)&lp;
                    }
                }
            }
        }
    }
}

// ============================================================================
// QK^T scores kernel (fp16 Q hi x K hi/lo, 2 combos, K=64 single shot)
// ============================================================================
#define QKROWB 144
#define QKPLANE (128*QKROWB)
#define QK_SMEM (3*QKPLANE)

__global__ void __launch_bounds__(256, 2) qk_gemm_kernel(
    const __half* __restrict__ Qg,
    const __half* __restrict__ Kg, long PLK,
    float* __restrict__ S)
{
    extern __shared__ char smem[];
    const uint32_t sbase = smem_u32(smem);

    const int z  = blockIdx.z;
    const int m0 = blockIdx.y * 128;
    const int n0 = blockIdx.x * 128;
    const __half* Qz = Qg + ((size_t)z * CS + m0) * CDK;
    const __half* Kz = Kg + ((size_t)z * CS + n0) * CDK;
    float* Sz = S + (size_t)z * CS * CS;

    const int tid  = threadIdx.x;
    const int warp = tid >> 5;
    const int lane = tid & 31;
    const int wm   = warp & 3;
    const int wn   = warp >> 2;
    const int lane8 = lane & 7;
    const int lg    = lane >> 3;

    #pragma unroll
    for (int i = 0; i < 12; i++) {
        int seg = i * 256 + tid;
        int p   = seg >> 10;
        int r   = (seg >> 3) & 127;
        int c   = seg & 7;
        const __half* src;
        if (p == 0)      src = Qz + (size_t)r * CDK + c * 8;
        else if (p == 1) src = Kz + (size_t)r * CDK + c * 8;
        else             src = Kz + PLK + (size_t)r * CDK + c * 8;
        cp_async16(sbase + p * QKPLANE + r * QKROWB + c * 16, src);
    }
    cp_commit();
    cp_wait<0>();
    __syncthreads();

    float acc[2][8][4];
    #pragma unroll
    for (int i = 0; i < 2; i++)
        #pragma unroll
        for (int j = 0; j < 8; j++)
            #pragma unroll
            for (int c = 0; c < 4; c++) acc[i][j][c] = 0.f;

    #pragma unroll
    for (int ks = 0; ks < 4; ks++) {
        uint32_t qf[2][4];
        #pragma unroll
        for (int tm = 0; tm < 2; tm++) {
            int row = wm * 32 + tm * 16 + lane8 + (lg & 1) * 8;
            int col = ks * 32 + (lg >> 1) * 16;
            ldm4(qf[tm], sbase + row * QKROWB + col);
        }
        #pragma unroll
        for (int tp = 0; tp < 4; tp++) {
            uint32_t kh[4], kl[4];
            int row = wn * 64 + tp * 16 + lane8 + (lg >> 1) * 8;
            int col = ks * 32 + (lg & 1) * 16;
            uint32_t addr = sbase + QKPLANE + row * QKROWB + col;
            ldm4(kh, addr);
            ldm4(kl, addr + QKPLANE);
            #pragma unroll
            for (int tm = 0; tm < 2; tm++) {
                #pragma unroll
                for (int h2 = 0; h2 < 2; h2++) {
                    float* c = acc[tm][tp * 2 + h2];
                    mma_f16(c, qf[tm], kh + h2 * 2);
                    mma_f16(c, qf[tm], kl + h2 * 2);
                }
            }
        }
    }

    const int gid = lane >> 2;
    const int tig = lane & 3;
    #pragma unroll
    for (int tm = 0; tm < 2; tm++) {
        #pragma unroll
        for (int tn = 0; tn < 8; tn++) {
            float* c = acc[tm][tn];
            const int m = m0 + wm * 32 + tm * 16 + gid;
            const int n = n0 + wn * 64 + tn * 8 + tig * 2;
            *(float2*)(Sz + (size_t)m * CS + n) =
                make_float2(c[0] * 0.125f, c[1] * 0.125f);
            *(float2*)(Sz + (size_t)(m + 8) * CS + n) =
                make_float2(c[2] * 0.125f, c[3] * 0.125f);
        }
    }
}

// ============================================================================
// Row-ops: warp per row, no barriers, no smem (R8, measured good)
// ============================================================================
__global__ void __launch_bounds__(256) rowops_kernel(
    const float* __restrict__ scores, const float* __restrict__ gammas,
    __half* __restrict__ Pout)
{
    const long gid = (long)blockIdx.x * 8 + (threadIdx.x >> 5);
    const int lane = threadIdx.x & 31;
    const int i = (int)(gid & (CS - 1));
    const int h = (int)((gid >> 10) & (CH - 1));
    const float* row = scores + gid * CS;

    float s[32];
    #pragma unroll
    for (int g = 0; g < 8; g++)
        *(float4*)(s + g * 4) = *(const float4*)(row + g * 128 + lane * 4);

    float mx = s[0];
    #pragma unroll
    for (int q = 1; q < 32; q++) mx = fmaxf(mx, s[q]);
    #pragma unroll
    for (int o = 16; o; o >>= 1) mx = fmaxf(mx, __shfl_xor_sync(0xffffffffu, mx, o));

    float e[32];
    float zl = 0.f;
    #pragma unroll
    for (int q = 0; q < 32; q++) { e[q] = __expf(s[q] - mx); zl += e[q]; }
    #pragma unroll
    for (int o = 16; o; o >>= 1) zl += __shfl_xor_sync(0xffffffffu, zl, o);
    const float invZ = 1.f / zl;

    const int glim = i >> 7;

    float carry = 0.f;
    #pragma unroll
    for (int g = 0; g < 8; g++) {
        if (g <= glim) {
            const int j0 = g * 128 + lane * 4;
            float m0 = (j0 + 0 <= i) ? e[g*4+0] : 0.f;
            float m1 = (j0 + 1 <= i) ? e[g*4+1] : 0.f;
            float m2 = (j0 + 2 <= i) ? e[g*4+2] : 0.f;
            float m3 = (j0 + 3 <= i) ? e[g*4+3] : 0.f;
            float l0 = m0, l1 = l0 + m1, l2 = l1 + m2, l3 = l2 + m3;
            float x = l3;
            #pragma unroll
            for (int d = 1; d < 32; d <<= 1) {
                float y = __shfl_up_sync(0xffffffffu, x, d);
                if (lane >= d) x += y;
            }
            float excl = x - l3;
            float tot  = __shfl_sync(0xffffffffu, x, 31);
            e[g*4+0] = carry + excl + l0;
            e[g*4+1] = carry + excl + l1;
            e[g*4+2] = carry + excl + l2;
            e[g*4+3] = carry + excl + l3;
            carry += tot;
        }
    }
    const float T = carry;

    const float g_  = gammas[h];
    const float gamma = -((g_ > 20.f) ? g_ : log1pf(__expf(g_)));
    const float NEG_INF = -__int_as_float(0x7f800000);
    #pragma unroll
    for (int g = 0; g < 8; g++) {
        if (g <= glim) {
            const int j0 = g * 128 + lane * 4;
            #pragma unroll
            for (int q = 0; q < 4; q++) {
                const int j = j0 + q;
                if (j <= i) {
                    float d2 = fmaxf((T - e[g*4+q]) * invZ * (float)(i - j), 0.f);
                    float eff = fminf(fmaxf(__expf(gamma * sqrtf(d2)), 1e-5f), 1e5f);
                    s[g*4+q] = s[g*4+q] * eff;
                } else {
                    s[g*4+q] = NEG_INF;
                }
            }
        }
    }

    float mx2 = NEG_INF;
    #pragma unroll
    for (int g = 0; g < 8; g++)
        if (g <= glim) {
            #pragma unroll
            for (int q = 0; q < 4; q++) mx2 = fmaxf(mx2, s[g*4+q]);
        }
    #pragma unroll
    for (int o = 16; o; o >>= 1) mx2 = fmaxf(mx2, __shfl_xor_sync(0xffffffffu, mx2, o));

    float z2 = 0.f;
    #pragma unroll
    for (int g = 0; g < 8; g++)
        if (g <= glim) {
            #pragma unroll
            for (int q = 0; q < 4; q++) {
                s[g*4+q] = __expf(s[g*4+q] - mx2);
                z2 += s[g*4+q];
            }
        }
    #pragma unroll
    for (int o = 16; o; o >>= 1) z2 += __shfl_xor_sync(0xffffffffu, z2, o);
    const float invZ2 = 1.f / z2;

    __half* prow = Pout + gid * CS;
    #pragma unroll
    for (int g = 0; g < 8; g++) {
        if (g <= glim) {
            __half2 p0 = __floats2half2_rn(s[g*4+0] * invZ2, s[g*4+1] * invZ2);
            __half2 p1 = __floats2half2_rn(s[g*4+2] * invZ2, s[g*4+3] * invZ2);
            uint2 pk;
            pk.x = *(uint32_t*)&p0;
            pk.y = *(uint32_t*)&p1;
            *(uint2*)(prow + g * 128 + lane * 4) = pk;
        }
    }
}

// ============================================================================
// AV HMMA (triangular)
// ============================================================================
#define AROWB 144
#define AP_BYTES (128*AROWB)
#define AV_BYTES (2*64*AROWB)
#define AV_BUF (AP_BYTES + AV_BYTES)
#define AV_SMEM (2*AV_BUF)

__global__ void __launch_bounds__(256, 2) av_mma_kernel(
    const __half* __restrict__ Pg, const __half* __restrict__ Vt, long PLV,
    __nv_bfloat16* __restrict__ Cc, long PLC)
{
    extern __shared__ char smem[];
    const uint32_t sbase = smem_u32(smem);

    const int z  = blockIdx.z;
    const int m0 = blockIdx.y * 128;
    const __half* Pz = Pg + (size_t)z * CS * CS;
    const __half* Vz = Vt + (size_t)z * CDK * CS;

    const int tid  = threadIdx.x;
    const int warp = tid >> 5;
    const int lane = tid & 31;
    const int wm   = warp & 3;
    const int wn   = warp >> 2;
    const int lane8 = lane & 7;
    const int lg    = lane >> 3;

    float acc[2][4][4];
    #pragma unroll
    for (int i = 0; i < 2; i++)
        #pragma unroll
        for (int j = 0; j < 4; j++)
            #pragma unroll
            for (int c = 0; c < 4; c++) acc[i][j][c] = 0.f;

    const int nch = 2 * (blockIdx.y + 1);

    auto load_chunk = [&](int ic, int b) {
        const int k0 = ic * 64;
        #pragma unroll
        for (int i = 0; i < 8; i++) {
            int seg = i * 256 + tid;
            int part = seg >> 10;
            int r    = (seg >> 3) & 127;
            int c    = seg & 7;
            uint32_t dstb = sbase + b * AV_BUF;
            if (part == 0) {
                const __half* src = Pz + (size_t)(m0 + r) * CS + k0 + c * 8;
                cp_async16(dstb + r * AROWB + c * 16, src);
            } else {
                int pl = r >> 6, rr2 = r & 63;
                const __half* src = Vz + (size_t)pl * PLV + (size_t)rr2 * CS + k0 + c * 8;
                cp_async16(dstb + AP_BYTES + pl * (64 * AROWB) + rr2 * AROWB + c * 16, src);
            }
        }
        cp_commit();
    };

    load_chunk(0, 0);
    load_chunk(1, 1);

    for (int ic = 0; ic < nch; ic++) {
        const int b = ic & 1;
        if (ic == nch - 1) cp_wait<0>(); else cp_wait<1>();
        __syncthreads();

        const uint32_t bb = sbase + b * AV_BUF;
        #pragma unroll
        for (int kk = 0; kk < 4; kk++) {
            uint32_t af[2][4];
            #pragma unroll
            for (int tm = 0; tm < 2; tm++) {
                int row = wm * 32 + tm * 16 + lane8 + (lg & 1) * 8;
                int col = kk * 32 + (lg >> 1) * 16;
                ldm4(af[tm], bb + row * AROWB + col);
            }
            #pragma unroll
            for (int tp = 0; tp < 2; tp++) {
                uint32_t bhf[4], blf[4];
                int row = wn * 32 + tp * 16 + lane8 + (lg >> 1) * 8;
                int col = kk * 32 + (lg & 1) * 16;
                uint32_t addr = bb + AP_BYTES + row * AROWB + col;
                ldm4(bhf, addr);
                ldm4(blf, addr + 64 * AROWB);
                #pragma unroll
                for (int tm = 0; tm < 2; tm++) {
                    #pragma unroll
                    for (int h2 = 0; h2 < 2; h2++) {
                        float* c = acc[tm][tp * 2 + h2];
                        mma_f16(c, af[tm], bhf + h2 * 2);
                        mma_f16(c, af[tm], blf + h2 * 2);
                    }
                }
            }
        }
        __syncthreads();
        if (ic + 2 < nch) load_chunk(ic + 2, b);
    }

    const int gid = lane >> 2;
    const int tig = lane & 3;
    const int b_ = z >> 4;
    const int h  = z & 15;
    #pragma unroll
    for (int tm = 0; tm < 2; tm++) {
        #pragma unroll
        for (int tn = 0; tn < 4; tn++) {
            float* c = acc[tm][tn];
            const int m = m0 + wm * 32 + tm * 16 + gid;
            const int n = wn * 32 + tn * 8 + tig * 2;
            #pragma unroll
            for (int rr = 0; rr < 2; rr++) {
                const int s = m + rr * 8;
                const float va = c[rr * 2 + 0], vb = c[rr * 2 + 1];
                size_t idx = ((size_t)(b_ * CS + s)) * CDM + h * CDK + n;
                __nv_bfloat16 h2[2], l2[2];
                h2[0] = __float2bfloat16(va);
                h2[1] = __float2bfloat16(vb);
                l2[0] = __float2bfloat16(va - __bfloat162float(h2[0]));
                l2[1] = __float2bfloat16(vb - __bfloat162float(h2[1]));
                *(uint32_t*)(Cc + idx)       = *(uint32_t*)h2;
                *(uint32_t*)(Cc + PLC + idx) = *(uint32_t*)l2;
            }
        }
    }
}

// ============================================================================
// Launch sequence
// ============================================================================
extern "C" void kernel_launch(void* const* d_in, const int* in_sizes, int n_in,
                              void* d_out, int out_size)
{
    const float* q      = (const float*)d_in[0];
    const float* k      = (const float*)d_in[1];
    const float* v      = (const float*)d_in[2];
    const float* Wq     = (const float*)d_in[3];
    const float* bq     = (const float*)d_in[4];
    const float* Wk     = (const float*)d_in[5];
    const float* bk     = (const float*)d_in[6];
    const float* Wv     = (const float*)d_in[7];
    const float* bv     = (const float*)d_in[8];
    const float* Wo     = (const float*)d_in[9];
    const float* bo     = (const float*)d_in[10];
    const float* gammas = (const float*)d_in[11];
    float* out = (float*)d_out;

    float *sc;
    __half *ps, *vts, *qhs, *khs;
    __nv_bfloat16 *qs, *ks, *vs, *ccs, *wqs, *wks, *wvs, *wos;
    cudaGetSymbolAddress((void**)&sc,  g_scores);
    cudaGetSymbolAddress((void**)&ps,  g_ps);
    cudaGetSymbolAddress((void**)&vts, g_vts);
    cudaGetSymbolAddress((void**)&qhs, g_qhs);
    cudaGetSymbolAddress((void**)&khs, g_khs);
    cudaGetSymbolAddress((void**)&qs,  g_qs);
    cudaGetSymbolAddress((void**)&ks,  g_ks);
    cudaGetSymbolAddress((void**)&vs,  g_vs);
    cudaGetSymbolAddress((void**)&ccs, g_ccs);
    cudaGetSymbolAddress((void**)&wqs, g_wqs);
    cudaGetSymbolAddress((void**)&wks, g_wks);
    cudaGetSymbolAddress((void**)&wvs, g_wvs);
    cudaGetSymbolAddress((void**)&wos, g_wos);

    cudaFuncSetAttribute(mma_gemm_kernel<0>, cudaFuncAttributeMaxDynamicSharedMemorySize, MM_SMEM);
    cudaFuncSetAttribute(mma_gemm_kernel<3>, cudaFuncAttributeMaxDynamicSharedMemorySize, MM_SMEM);
    cudaFuncSetAttribute(mma_gemm_kernel<4>, cudaFuncAttributeMaxDynamicSharedMemorySize, MM_SMEM);
    cudaFuncSetAttribute(mma_gemm_kernel<5>, cudaFuncAttributeMaxDynamicSharedMemorySize, MM_SMEM);
    cudaFuncSetAttribute(qk_gemm_kernel,   cudaFuncAttributeMaxDynamicSharedMemorySize, QK_SMEM);
    cudaFuncSetAttribute(av_mma_kernel,    cudaFuncAttributeMaxDynamicSharedMemorySize, AV_SMEM);

    const int  M    = CB * CS;              // 4096
    const long nBig = (long)M * CDM;        // 4 M elems
    const long nW   = (long)CDM * CDM;      // 1 M elems
    const long nH   = (long)CBH * CS * CDK; // 4 M elems

    // split inputs + weights to bf16 hi/lo planes
    split_bf16_kernel<<<(unsigned)(nBig/1024), 256>>>(q,  qs,  nBig);
    split_bf16_kernel<<<(unsigned)(nBig/1024), 256>>>(k,  ks,  nBig);
    split_bf16_kernel<<<(unsigned)(nBig/1024), 256>>>(v,  vs,  nBig);
    split_bf16_kernel<<<(unsigned)(nW/1024),   256>>>(Wq, wqs, nW);
    split_bf16_kernel<<<(unsigned)(nW/1024),   256>>>(Wk, wks, nW);
    split_bf16_kernel<<<(unsigned)(nW/1024),   256>>>(Wv, wvs, nW);
    split_bf16_kernel<<<(unsigned)(nW/1024),   256>>>(Wo, wos, nW);

    // Q -> fp16 single plane; K -> fp16 hi/lo planes (head-scattered)
    mma_gemm_kernel<4><<<dim3(CDM/128, M/128), 256, MM_SMEM>>>(
        qs, nBig, wqs, nW, bq, nullptr, qhs, 0, M, CDM, CDM, 1.f);
    mma_gemm_kernel<5><<<dim3(CDM/128, M/128), 256, MM_SMEM>>>(
        ks, nBig, wks, nW, bk, nullptr, khs, nH, M, CDM, CDM, 1.f);
    // V -> fp16 split planes, transposed per head
    mma_gemm_kernel<3><<<dim3(CDM/128, M/128), 256, MM_SMEM>>>(
        vs, nBig, wvs, nW, bv, nullptr, vts, nH, M, CDM, CDM, 1.f);

    // scores = Qh @ Kh^T / 8 (fp32), batched over bh
    qk_gemm_kernel<<<dim3(CS/128, CS/128, CBH), 256, QK_SMEM>>>(qhs, khs, nH, sc);

    // row ops (warp per row) -> fp16 P (causal-limited writes)
    rowops_kernel<<<CBH * CS / 8, 256>>>(sc, gammas, ps);

    // AV (triangular) -> concat bf16 split planes
    av_mma_kernel<<<dim3(1, CS/128, CBH), 256, AV_SMEM>>>(ps, vts, nH, ccs, nBig);

    // output projection
    mma_gemm_kernel<0><<<dim3(CDM/128, M/128), 256, MM_SMEM>>>(
        ccs, nBig, wos, nW, bo, out, nullptr, 0, M, CDM, CDM, 1.f);
}

// round 10
// speedup vs baseline: 1.4899x; 1.1968x over previous
#include <cuda_runtime.h>
#include <cuda_bf16.h>
#include <cuda_fp16.h>
#include <math.h>
#include <stdint.h>

// Problem constants
#define CB   4
#define CS   1024
#define CDM  1024
#define CH   16
#define CDK  64
#define CBH  (CB*CH)

// ---------------- scratch (device globals: allocation-free) ----------------
__device__ float g_scores[(size_t)CBH*CS*CS];            // 256 MB fp32
__device__ __half g_ps [(size_t)CBH*CS*CS];              // 128 MB fp16 (P)
__device__ __half g_vts[2*(size_t)CBH*CDK*CS];           // V^T fp16 hi/lo
__device__ __half g_qhs[(size_t)CBH*CS*CDK];             // Q fp16 (hi only)
__device__ __half g_khs[2*(size_t)CBH*CS*CDK];           // K fp16 hi/lo
__device__ __half g_qs [(size_t)CB*CS*CDM];              // activations fp16 hi
__device__ __half g_ks [(size_t)CB*CS*CDM];
__device__ __half g_vs [(size_t)CB*CS*CDM];
__device__ __half g_ccs[(size_t)CB*CS*CDM];              // concat fp16 hi
__device__ __half g_wqs[2*(size_t)CDM*CDM];              // weights fp16 hi/lo
__device__ __half g_wks[2*(size_t)CDM*CDM];
__device__ __half g_wvs[2*(size_t)CDM*CDM];
__device__ __half g_wos[2*(size_t)CDM*CDM];

// ============================================================================
// helpers
// ============================================================================
__device__ __forceinline__ uint32_t smem_u32(const void* p) {
    uint32_t a;
    asm("{ .reg .u64 t; cvta.to.shared.u64 t, %1; cvt.u32.u64 %0, t; }"
        : "=r"(a) : "l"(p));
    return a;
}
__device__ __forceinline__ void cp_async16(uint32_t dst, const void* src) {
    asm volatile("cp.async.cg.shared.global [%0], [%1], 16;"
                 :: "r"(dst), "l"(src) : "memory");
}
__device__ __forceinline__ void cp_commit() {
    asm volatile("cp.async.commit_group;" ::: "memory");
}
template<int N>
__device__ __forceinline__ void cp_wait() {
    asm volatile("cp.async.wait_group %0;" :: "n"(N) : "memory");
}
__device__ __forceinline__ void ldm4(uint32_t* r, uint32_t addr) {
    asm volatile("ldmatrix.sync.aligned.m8n8.x4.shared.b16 {%0,%1,%2,%3}, [%4];"
                 : "=r"(r[0]), "=r"(r[1]), "=r"(r[2]), "=r"(r[3]) : "r"(addr));
}
__device__ __forceinline__ void mma_f16(float* c, const uint32_t* a, const uint32_t* b) {
    asm volatile(
        "mma.sync.aligned.m16n8k16.row.col.f32.f16.f16.f32 "
        "{%0,%1,%2,%3}, {%4,%5,%6,%7}, {%8,%9}, {%0,%1,%2,%3};"
        : "+f"(c[0]), "+f"(c[1]), "+f"(c[2]), "+f"(c[3])
        : "r"(a[0]), "r"(a[1]), "r"(a[2]), "r"(a[3]), "r"(b[0]), "r"(b[1]));
}

// ============================================================================
// fp32 -> fp16 (hi only) for activations
// ============================================================================
__global__ void __launch_bounds__(256) cvt_f16_kernel(
    const float* __restrict__ x, __half* __restrict__ out, long n)
{
    long i = ((long)blockIdx.x * blockDim.x + threadIdx.x) * 4;
    if (i >= n) return;
    float4 v = *(const float4*)(x + i);
    __half h[4];
    h[0] = __float2half(v.x); h[1] = __float2half(v.y);
    h[2] = __float2half(v.z); h[3] = __float2half(v.w);
    *(uint2*)(out + i) = *(uint2*)h;
}

// fp32 -> fp16 hi/lo planes for weights
__global__ void __launch_bounds__(256) split_f16_kernel(
    const float* __restrict__ x, __half* __restrict__ out, long n)
{
    long i = ((long)blockIdx.x * blockDim.x + threadIdx.x) * 4;
    if (i >= n) return;
    float4 v = *(const float4*)(x + i);
    float f[4] = {v.x, v.y, v.z, v.w};
    __half h[4], l[4];
    #pragma unroll
    for (int j = 0; j < 4; j++) {
        h[j] = __float2half(f[j]);
        l[j] = __float2half(f[j] - __half2float(h[j]));
    }
    *(uint2*)(out + i)     = *(uint2*)h;
    *(uint2*)(out + n + i) = *(uint2*)l;
}

// ============================================================================
// HMMA GEMM (fp16, 2 combos: Ah*Bh + Ah*Bl, fp32 accumulate)
// A: fp16 hi plane only. B: fp16 hi/lo planes (lo at B+loB).
// OUT_MODE 0: fp32 row-major [M,N]
// OUT_MODE 3: fp16 hi/lo planes, transposed head-scatter
// OUT_MODE 4: fp16 single plane, head-scatter
// OUT_MODE 5: fp16 hi/lo planes, head-scatter
// ============================================================================
#define ROWB 80
#define PLANE 10240
#define BUF   (3*PLANE)          // Ah, Bh, Bl = 30720
#define MM_SMEM (2*BUF)          // 61440

template<int OUT_MODE>
__global__ void __launch_bounds__(256, 2) mma_gemm_kernel(
    const __half* __restrict__ A,
    const __half* __restrict__ B, long loB,
    const float* __restrict__ bias, float* __restrict__ C,
    void* __restrict__ Cpl, long PL,
    int M, int N, int K, float alpha)
{
    extern __shared__ char smem[];
    const uint32_t sbase = smem_u32(smem);

    const int m0 = blockIdx.y * 128;
    const int n0 = blockIdx.x * 128;

    const int tid  = threadIdx.x;
    const int warp = tid >> 5;
    const int lane = tid & 31;
    const int wm   = warp & 3;
    const int wn   = warp >> 2;
    const int lane8 = lane & 7;
    const int lg    = lane >> 3;

    const __half* bases[3];
    bases[0] = A + (size_t)m0 * K;
    bases[1] = B + (size_t)n0 * K;
    bases[2] = bases[1] + loB;

    float acc[2][8][4];
    #pragma unroll
    for (int i = 0; i < 2; i++)
        #pragma unroll
        for (int j = 0; j < 8; j++)
            #pragma unroll
            for (int c = 0; c < 4; c++) acc[i][j][c] = 0.f;

    const int nch = K >> 5;

    auto load_chunk = [&](int ic, int b) {
        const int k0 = ic * 32;
        #pragma unroll
        for (int i = 0; i < 6; i++) {
            int seg = i * 256 + tid;           // 0..1535
            int p   = seg >> 9;                // plane 0..2
            int r   = (seg >> 2) & 127;        // row
            int c   = seg & 3;                 // 16B col
            const __half* src = bases[p] + (size_t)r * K + k0 + c * 8;
            uint32_t dst = sbase + b * BUF + p * PLANE + r * ROWB + c * 16;
            cp_async16(dst, src);
        }
        cp_commit();
    };

    load_chunk(0, 0);
    if (nch > 1) load_chunk(1, 1);

    for (int ic = 0; ic < nch; ic++) {
        const int b = ic & 1;
        if (ic == nch - 1) cp_wait<0>(); else cp_wait<1>();
        __syncthreads();

        const uint32_t bb = sbase + b * BUF;
        #pragma unroll
        for (int kk = 0; kk < 2; kk++) {
            uint32_t ah[2][4];
            #pragma unroll
            for (int tm = 0; tm < 2; tm++) {
                int row = wm * 32 + tm * 16 + lane8 + (lg & 1) * 8;
                int col = kk * 32 + (lg >> 1) * 16;
                ldm4(ah[tm], bb + row * ROWB + col);
            }
            #pragma unroll
            for (int tp = 0; tp < 4; tp++) {
                uint32_t bhf[4], blf[4];
                int row = wn * 64 + tp * 16 + lane8 + (lg >> 1) * 8;
                int col = kk * 32 + (lg & 1) * 16;
                uint32_t addr = bb + PLANE + row * ROWB + col;
                ldm4(bhf, addr);
                ldm4(blf, addr + PLANE);
                #pragma unroll
                for (int tm = 0; tm < 2; tm++) {
                    #pragma unroll
                    for (int h2 = 0; h2 < 2; h2++) {
                        float* c = acc[tm][tp * 2 + h2];
                        mma_f16(c, ah[tm], bhf + h2 * 2);
                        mma_f16(c, ah[tm], blf + h2 * 2);
                    }
                }
            }
        }
        __syncthreads();
        if (ic + 2 < nch) load_chunk(ic + 2, b);
    }

    // ---- epilogue ----
    const int gid = lane >> 2;
    const int tig = lane & 3;
    #pragma unroll
    for (int tm = 0; tm < 2; tm++) {
        #pragma unroll
        for (int tn = 0; tn < 8; tn++) {
            float* c = acc[tm][tn];
            const int m = m0 + wm * 32 + tm * 16 + gid;
            const int n = n0 + wn * 64 + tn * 8 + tig * 2;
            float b0 = 0.f, b1 = 0.f;
            if (bias) { b0 = bias[n]; b1 = bias[n + 1]; }
            float v00 = c[0] * alpha + b0, v01 = c[1] * alpha + b1;
            float v10 = c[2] * alpha + b0, v11 = c[3] * alpha + b1;
            if (OUT_MODE == 0) {
                *(float2*)(C + (size_t)m * N + n)       = make_float2(v00, v01);
                *(float2*)(C + (size_t)(m + 8) * N + n) = make_float2(v10, v11);
            } else if (OUT_MODE == 3) { // fp16 transposed planes
                __half* P = (__half*)Cpl;
                const int h  = n >> 6;
                const int dk = n & 63;
                #pragma unroll
                for (int rr = 0; rr < 2; rr++) {
                    const int mm = m + rr * 8;
                    const float va = rr ? v10 : v00, vb = rr ? v11 : v01;
                    const int b_ = mm >> 10, s = mm & 1023;
                    size_t base = (((size_t)(b_ * CH + h)) * CDK + dk) * CS + s;
                    __half ha = __float2half(va);
                    __half la = __float2half(va - __half2float(ha));
                    __half hb = __float2half(vb);
                    __half lb = __float2half(vb - __half2float(hb));
                    P[base]           = ha;
                    P[base + PL]      = la;
                    P[base + CS]      = hb;
                    P[base + CS + PL] = lb;
                }
            } else { // OUT_MODE 4/5: fp16 plane(s), head-scatter row-major
                __half* P = (__half*)Cpl;
                const int h  = n >> 6;
                const int dk = n & 63;
                #pragma unroll
                for (int rr = 0; rr < 2; rr++) {
                    const int mm = m + rr * 8;
                    const float va = rr ? v10 : v00, vb = rr ? v11 : v01;
                    const int b_ = mm >> 10, s = mm & 1023;
                    size_t idx = (((size_t)(b_ * CH + h)) * CS + s) * CDK + dk;
                    __half ha = __float2half(va);
                    __half hb = __float2half(vb);
                    __half2 hp = __halves2half2(ha, hb);
                    *(uint32_t*)(P + idx) = *(uint32_t*)&hp;
                    if (OUT_MODE == 5) {
                        __half la = __float2half(va - __half2float(ha));
                        __half lb = __float2half(vb - __half2float(hb));
                        __half2 lp = __halves2half2(la, lb);
                        *(uint32_t*)(P + PL + idx) = *(uint32_t*)&lp;
                    }
                }
            }
        }
    }
}

// ============================================================================
// QK^T scores kernel (fp16 Q hi x K hi/lo, 2 combos, K=64 single shot)
// ============================================================================
#define QKROWB 144
#define QKPLANE (128*QKROWB)
#define QK_SMEM (3*QKPLANE)

__global__ void __launch_bounds__(256, 2) qk_gemm_kernel(
    const __half* __restrict__ Qg,
    const __half* __restrict__ Kg, long PLK,
    float* __restrict__ S)
{
    extern __shared__ char smem[];
    const uint32_t sbase = smem_u32(smem);

    const int z  = blockIdx.z;
    const int m0 = blockIdx.y * 128;
    const int n0 = blockIdx.x * 128;
    const __half* Qz = Qg + ((size_t)z * CS + m0) * CDK;
    const __half* Kz = Kg + ((size_t)z * CS + n0) * CDK;
    float* Sz = S + (size_t)z * CS * CS;

    const int tid  = threadIdx.x;
    const int warp = tid >> 5;
    const int lane = tid & 31;
    const int wm   = warp & 3;
    const int wn   = warp >> 2;
    const int lane8 = lane & 7;
    const int lg    = lane >> 3;

    #pragma unroll
    for (int i = 0; i < 12; i++) {
        int seg = i * 256 + tid;
        int p   = seg >> 10;
        int r   = (seg >> 3) & 127;
        int c   = seg & 7;
        const __half* src;
        if (p == 0)      src = Qz + (size_t)r * CDK + c * 8;
        else if (p == 1) src = Kz + (size_t)r * CDK + c * 8;
        else             src = Kz + PLK + (size_t)r * CDK + c * 8;
        cp_async16(sbase + p * QKPLANE + r * QKROWB + c * 16, src);
    }
    cp_commit();
    cp_wait<0>();
    __syncthreads();

    float acc[2][8][4];
    #pragma unroll
    for (int i = 0; i < 2; i++)
        #pragma unroll
        for (int j = 0; j < 8; j++)
            #pragma unroll
            for (int c = 0; c < 4; c++) acc[i][j][c] = 0.f;

    #pragma unroll
    for (int ks = 0; ks < 4; ks++) {
        uint32_t qf[2][4];
        #pragma unroll
        for (int tm = 0; tm < 2; tm++) {
            int row = wm * 32 + tm * 16 + lane8 + (lg & 1) * 8;
            int col = ks * 32 + (lg >> 1) * 16;
            ldm4(qf[tm], sbase + row * QKROWB + col);
        }
        #pragma unroll
        for (int tp = 0; tp < 4; tp++) {
            uint32_t kh[4], kl[4];
            int row = wn * 64 + tp * 16 + lane8 + (lg >> 1) * 8;
            int col = ks * 32 + (lg & 1) * 16;
            uint32_t addr = sbase + QKPLANE + row * QKROWB + col;
            ldm4(kh, addr);
            ldm4(kl, addr + QKPLANE);
            #pragma unroll
            for (int tm = 0; tm < 2; tm++) {
                #pragma unroll
                for (int h2 = 0; h2 < 2; h2++) {
                    float* c = acc[tm][tp * 2 + h2];
                    mma_f16(c, qf[tm], kh + h2 * 2);
                    mma_f16(c, qf[tm], kl + h2 * 2);
                }
            }
        }
    }

    const int gid = lane >> 2;
    const int tig = lane & 3;
    #pragma unroll
    for (int tm = 0; tm < 2; tm++) {
        #pragma unroll
        for (int tn = 0; tn < 8; tn++) {
            float* c = acc[tm][tn];
            const int m = m0 + wm * 32 + tm * 16 + gid;
            const int n = n0 + wn * 64 + tn * 8 + tig * 2;
            *(float2*)(Sz + (size_t)m * CS + n) =
                make_float2(c[0] * 0.125f, c[1] * 0.125f);
            *(float2*)(Sz + (size_t)(m + 8) * CS + n) =
                make_float2(c[2] * 0.125f, c[3] * 0.125f);
        }
    }
}

// ============================================================================
// Row-ops: warp per row, no barriers, no smem
// ============================================================================
__global__ void __launch_bounds__(256) rowops_kernel(
    const float* __restrict__ scores, const float* __restrict__ gammas,
    __half* __restrict__ Pout)
{
    const long gid = (long)blockIdx.x * 8 + (threadIdx.x >> 5);
    const int lane = threadIdx.x & 31;
    const int i = (int)(gid & (CS - 1));
    const int h = (int)((gid >> 10) & (CH - 1));
    const float* row = scores + gid * CS;

    float s[32];
    #pragma unroll
    for (int g = 0; g < 8; g++)
        *(float4*)(s + g * 4) = *(const float4*)(row + g * 128 + lane * 4);

    float mx = s[0];
    #pragma unroll
    for (int q = 1; q < 32; q++) mx = fmaxf(mx, s[q]);
    #pragma unroll
    for (int o = 16; o; o >>= 1) mx = fmaxf(mx, __shfl_xor_sync(0xffffffffu, mx, o));

    float e[32];
    float zl = 0.f;
    #pragma unroll
    for (int q = 0; q < 32; q++) { e[q] = __expf(s[q] - mx); zl += e[q]; }
    #pragma unroll
    for (int o = 16; o; o >>= 1) zl += __shfl_xor_sync(0xffffffffu, zl, o);
    const float invZ = 1.f / zl;

    const int glim = i >> 7;

    float carry = 0.f;
    #pragma unroll
    for (int g = 0; g < 8; g++) {
        if (g <= glim) {
            const int j0 = g * 128 + lane * 4;
            float m0 = (j0 + 0 <= i) ? e[g*4+0] : 0.f;
            float m1 = (j0 + 1 <= i) ? e[g*4+1] : 0.f;
            float m2 = (j0 + 2 <= i) ? e[g*4+2] : 0.f;
            float m3 = (j0 + 3 <= i) ? e[g*4+3] : 0.f;
            float l0 = m0, l1 = l0 + m1, l2 = l1 + m2, l3 = l2 + m3;
            float x = l3;
            #pragma unroll
            for (int d = 1; d < 32; d <<= 1) {
                float y = __shfl_up_sync(0xffffffffu, x, d);
                if (lane >= d) x += y;
            }
            float excl = x - l3;
            float tot  = __shfl_sync(0xffffffffu, x, 31);
            e[g*4+0] = carry + excl + l0;
            e[g*4+1] = carry + excl + l1;
            e[g*4+2] = carry + excl + l2;
            e[g*4+3] = carry + excl + l3;
            carry += tot;
        }
    }
    const float T = carry;

    const float g_  = gammas[h];
    const float gamma = -((g_ > 20.f) ? g_ : log1pf(__expf(g_)));
    const float NEG_INF = -__int_as_float(0x7f800000);
    #pragma unroll
    for (int g = 0; g < 8; g++) {
        if (g <= glim) {
            const int j0 = g * 128 + lane * 4;
            #pragma unroll
            for (int q = 0; q < 4; q++) {
                const int j = j0 + q;
                if (j <= i) {
                    float d2 = fmaxf((T - e[g*4+q]) * invZ * (float)(i - j), 0.f);
                    float eff = fminf(fmaxf(__expf(gamma * sqrtf(d2)), 1e-5f), 1e5f);
                    s[g*4+q] = s[g*4+q] * eff;
                } else {
                    s[g*4+q] = NEG_INF;
                }
            }
        }
    }

    float mx2 = NEG_INF;
    #pragma unroll
    for (int g = 0; g < 8; g++)
        if (g <= glim) {
            #pragma unroll
            for (int q = 0; q < 4; q++) mx2 = fmaxf(mx2, s[g*4+q]);
        }
    #pragma unroll
    for (int o = 16; o; o >>= 1) mx2 = fmaxf(mx2, __shfl_xor_sync(0xffffffffu, mx2, o));

    float z2 = 0.f;
    #pragma unroll
    for (int g = 0; g < 8; g++)
        if (g <= glim) {
            #pragma unroll
            for (int q = 0; q < 4; q++) {
                s[g*4+q] = __expf(s[g*4+q] - mx2);
                z2 += s[g*4+q];
            }
        }
    #pragma unroll
    for (int o = 16; o; o >>= 1) z2 += __shfl_xor_sync(0xffffffffu, z2, o);
    const float invZ2 = 1.f / z2;

    __half* prow = Pout + gid * CS;
    #pragma unroll
    for (int g = 0; g < 8; g++) {
        if (g <= glim) {
            __half2 p0 = __floats2half2_rn(s[g*4+0] * invZ2, s[g*4+1] * invZ2);
            __half2 p1 = __floats2half2_rn(s[g*4+2] * invZ2, s[g*4+3] * invZ2);
            uint2 pk;
            pk.x = *(uint32_t*)&p0;
            pk.y = *(uint32_t*)&p1;
            *(uint2*)(prow + g * 128 + lane * 4) = pk;
        }
    }
}

// ============================================================================
// AV HMMA (triangular) -> concat fp16 single plane
// ============================================================================
#define AROWB 144
#define AP_BYTES (128*AROWB)
#define AV_BYTES (2*64*AROWB)
#define AV_BUF (AP_BYTES + AV_BYTES)
#define AV_SMEM (2*AV_BUF)

__global__ void __launch_bounds__(256, 2) av_mma_kernel(
    const __half* __restrict__ Pg, const __half* __restrict__ Vt, long PLV,
    __half* __restrict__ Cc)
{
    extern __shared__ char smem[];
    const uint32_t sbase = smem_u32(smem);

    const int z  = blockIdx.z;
    const int m0 = blockIdx.y * 128;
    const __half* Pz = Pg + (size_t)z * CS * CS;
    const __half* Vz = Vt + (size_t)z * CDK * CS;

    const int tid  = threadIdx.x;
    const int warp = tid >> 5;
    const int lane = tid & 31;
    const int wm   = warp & 3;
    const int wn   = warp >> 2;
    const int lane8 = lane & 7;
    const int lg    = lane >> 3;

    float acc[2][4][4];
    #pragma unroll
    for (int i = 0; i < 2; i++)
        #pragma unroll
        for (int j = 0; j < 4; j++)
            #pragma unroll
            for (int c = 0; c < 4; c++) acc[i][j][c] = 0.f;

    const int nch = 2 * (blockIdx.y + 1);

    auto load_chunk = [&](int ic, int b) {
        const int k0 = ic * 64;
        #pragma unroll
        for (int i = 0; i < 8; i++) {
            int seg = i * 256 + tid;
            int part = seg >> 10;
            int r    = (seg >> 3) & 127;
            int c    = seg & 7;
            uint32_t dstb = sbase + b * AV_BUF;
            if (part == 0) {
                const __half* src = Pz + (size_t)(m0 + r) * CS + k0 + c * 8;
                cp_async16(dstb + r * AROWB + c * 16, src);
            } else {
                int pl = r >> 6, rr2 = r & 63;
                const __half* src = Vz + (size_t)pl * PLV + (size_t)rr2 * CS + k0 + c * 8;
                cp_async16(dstb + AP_BYTES + pl * (64 * AROWB) + rr2 * AROWB + c * 16, src);
            }
        }
        cp_commit();
    };

    load_chunk(0, 0);
    load_chunk(1, 1);

    for (int ic = 0; ic < nch; ic++) {
        const int b = ic & 1;
        if (ic == nch - 1) cp_wait<0>(); else cp_wait<1>();
        __syncthreads();

        const uint32_t bb = sbase + b * AV_BUF;
        #pragma unroll
        for (int kk = 0; kk < 4; kk++) {
            uint32_t af[2][4];
            #pragma unroll
            for (int tm = 0; tm < 2; tm++) {
                int row = wm * 32 + tm * 16 + lane8 + (lg & 1) * 8;
                int col = kk * 32 + (lg >> 1) * 16;
                ldm4(af[tm], bb + row * AROWB + col);
            }
            #pragma unroll
            for (int tp = 0; tp < 2; tp++) {
                uint32_t bhf[4], blf[4];
                int row = wn * 32 + tp * 16 + lane8 + (lg >> 1) * 8;
                int col = kk * 32 + (lg & 1) * 16;
                uint32_t addr = bb + AP_BYTES + row * AROWB + col;
                ldm4(bhf, addr);
                ldm4(blf, addr + 64 * AROWB);
                #pragma unroll
                for (int tm = 0; tm < 2; tm++) {
                    #pragma unroll
                    for (int h2 = 0; h2 < 2; h2++) {
                        float* c = acc[tm][tp * 2 + h2];
                        mma_f16(c, af[tm], bhf + h2 * 2);
                        mma_f16(c, af[tm], blf + h2 * 2);
                    }
                }
            }
        }
        __syncthreads();
        if (ic + 2 < nch) load_chunk(ic + 2, b);
    }

    const int gid = lane >> 2;
    const int tig = lane & 3;
    const int b_ = z >> 4;
    const int h  = z & 15;
    #pragma unroll
    for (int tm = 0; tm < 2; tm++) {
        #pragma unroll
        for (int tn = 0; tn < 4; tn++) {
            float* c = acc[tm][tn];
            const int m = m0 + wm * 32 + tm * 16 + gid;
            const int n = wn * 32 + tn * 8 + tig * 2;
            #pragma unroll
            for (int rr = 0; rr < 2; rr++) {
                const int s = m + rr * 8;
                const float va = c[rr * 2 + 0], vb = c[rr * 2 + 1];
                size_t idx = ((size_t)(b_ * CS + s)) * CDM + h * CDK + n;
                __half2 hp = __floats2half2_rn(va, vb);
                *(uint32_t*)(Cc + idx) = *(uint32_t*)&hp;
            }
        }
    }
}

// ============================================================================
// Launch sequence
// ============================================================================
extern "C" void kernel_launch(void* const* d_in, const int* in_sizes, int n_in,
                              void* d_out, int out_size)
{
    const float* q      = (const float*)d_in[0];
    const float* k      = (const float*)d_in[1];
    const float* v      = (const float*)d_in[2];
    const float* Wq     = (const float*)d_in[3];
    const float* bq     = (const float*)d_in[4];
    const float* Wk     = (const float*)d_in[5];
    const float* bk     = (const float*)d_in[6];
    const float* Wv     = (const float*)d_in[7];
    const float* bv     = (const float*)d_in[8];
    const float* Wo     = (const float*)d_in[9];
    const float* bo     = (const float*)d_in[10];
    const float* gammas = (const float*)d_in[11];
    float* out = (float*)d_out;

    float *sc;
    __half *ps, *vts, *qhs, *khs, *qs, *ks, *vs, *ccs, *wqs, *wks, *wvs, *wos;
    cudaGetSymbolAddress((void**)&sc,  g_scores);
    cudaGetSymbolAddress((void**)&ps,  g_ps);
    cudaGetSymbolAddress((void**)&vts, g_vts);
    cudaGetSymbolAddress((void**)&qhs, g_qhs);
    cudaGetSymbolAddress((void**)&khs, g_khs);
    cudaGetSymbolAddress((void**)&qs,  g_qs);
    cudaGetSymbolAddress((void**)&ks,  g_ks);
    cudaGetSymbolAddress((void**)&vs,  g_vs);
    cudaGetSymbolAddress((void**)&ccs, g_ccs);
    cudaGetSymbolAddress((void**)&wqs, g_wqs);
    cudaGetSymbolAddress((void**)&wks, g_wks);
    cudaGetSymbolAddress((void**)&wvs, g_wvs);
    cudaGetSymbolAddress((void**)&wos, g_wos);

    cudaFuncSetAttribute(mma_gemm_kernel<0>, cudaFuncAttributeMaxDynamicSharedMemorySize, MM_SMEM);
    cudaFuncSetAttribute(mma_gemm_kernel<3>, cudaFuncAttributeMaxDynamicSharedMemorySize, MM_SMEM);
    cudaFuncSetAttribute(mma_gemm_kernel<4>, cudaFuncAttributeMaxDynamicSharedMemorySize, MM_SMEM);
    cudaFuncSetAttribute(mma_gemm_kernel<5>, cudaFuncAttributeMaxDynamicSharedMemorySize, MM_SMEM);
    cudaFuncSetAttribute(qk_gemm_kernel,   cudaFuncAttributeMaxDynamicSharedMemorySize, QK_SMEM);
    cudaFuncSetAttribute(av_mma_kernel,    cudaFuncAttributeMaxDynamicSharedMemorySize, AV_SMEM);

    const int  M    = CB * CS;              // 4096
    const long nBig = (long)M * CDM;        // 4 M elems
    const long nW   = (long)CDM * CDM;      // 1 M elems
    const long nH   = (long)CBH * CS * CDK; // 4 M elems

    // activations -> fp16 hi; weights -> fp16 hi/lo
    cvt_f16_kernel  <<<(unsigned)(nBig/1024), 256>>>(q,  qs,  nBig);
    cvt_f16_kernel  <<<(unsigned)(nBig/1024), 256>>>(k,  ks,  nBig);
    cvt_f16_kernel  <<<(unsigned)(nBig/1024), 256>>>(v,  vs,  nBig);
    split_f16_kernel<<<(unsigned)(nW/1024),   256>>>(Wq, wqs, nW);
    split_f16_kernel<<<(unsigned)(nW/1024),   256>>>(Wk, wks, nW);
    split_f16_kernel<<<(unsigned)(nW/1024),   256>>>(Wv, wvs, nW);
    split_f16_kernel<<<(unsigned)(nW/1024),   256>>>(Wo, wos, nW);

    // Q -> fp16 single plane; K -> fp16 hi/lo planes (head-scattered)
    mma_gemm_kernel<4><<<dim3(CDM/128, M/128), 256, MM_SMEM>>>(
        qs, wqs, nW, bq, nullptr, qhs, 0, M, CDM, CDM, 1.f);
    mma_gemm_kernel<5><<<dim3(CDM/128, M/128), 256, MM_SMEM>>>(
        ks, wks, nW, bk, nullptr, khs, nH, M, CDM, CDM, 1.f);
    // V -> fp16 split planes, transposed per head
    mma_gemm_kernel<3><<<dim3(CDM/128, M/128), 256, MM_SMEM>>>(
        vs, wvs, nW, bv, nullptr, vts, nH, M, CDM, CDM, 1.f);

    // scores = Qh @ Kh^T / 8 (fp32), batched over bh
    qk_gemm_kernel<<<dim3(CS/128, CS/128, CBH), 256, QK_SMEM>>>(qhs, khs, nH, sc);

    // row ops (warp per row) -> fp16 P (causal-limited writes)
    rowops_kernel<<<CBH * CS / 8, 256>>>(sc, gammas, ps);

    // AV (triangular) -> concat fp16 single plane
    av_mma_kernel<<<dim3(1, CS/128, CBH), 256, AV_SMEM>>>(ps, vts, nH, ccs);

    // output projection (cc fp16 hi x Wo hi/lo)
    mma_gemm_kernel<0><<<dim3(CDM/128, M/128), 256, MM_SMEM>>>(
        ccs, wos, nW, bo, out, nullptr, 0, M, CDM, CDM, 1.f);
}